// round 4
// baseline (speedup 1.0000x reference)
#include <cuda_runtime.h>
#include <cuda_bf16.h>
#include <math.h>

// Problem constants
#define BN     16384           // B*N tokens
#define DIM    512
#define NC     4096            // codes per stage
#define NQ     4               // stages
#define CBSZ   (NC * DIM)      // floats per stage codebook
#define QOUT_ELEMS  (BN * DIM)               // 8388608
#define IDX_OFF     QOUT_ELEMS
#define IDX_ELEMS   (BN * NQ)                // 65536
#define LOSS_OFF    (IDX_OFF + IDX_ELEMS)
#define OUT_FULL    (LOSS_OFF + NQ)

typedef unsigned long long ull;

// ---------------- device scratch (static globals; no runtime alloc) ----------
__device__ float  g_cbn[(size_t)NQ * CBSZ];     // normalized implicit codebooks (32MB)
__device__ float  g_xn [(size_t)BN * DIM];      // l2norm(residual) (32MB)
__device__ float  g_res[(size_t)BN * DIM];      // residual (32MB)
__device__ int    g_idx[BN];
__device__ double g_loss[NQ];

// ---------------- f32x2 helpers (Blackwell packed fp32) ----------------------
__device__ __forceinline__ ull dup2(float x) {
    ull r; asm("mov.b64 %0, {%1, %1};" : "=l"(r) : "f"(x)); return r;
}
__device__ __forceinline__ void fma2(ull& a, ull x, ull y) {
    asm("fma.rn.f32x2 %0, %1, %2, %0;" : "+l"(a) : "l"(x), "l"(y));
}
__device__ __forceinline__ float lo2(ull a) { return __uint_as_float((unsigned)a); }
__device__ __forceinline__ float hi2(ull a) { return __uint_as_float((unsigned)(a >> 32)); }

__device__ __forceinline__ float warp_sum(float v) {
    #pragma unroll
    for (int o = 16; o; o >>= 1) v += __shfl_xor_sync(0xffffffffu, v, o);
    return v;
}

// ---------------- misc small kernels -----------------------------------------
__global__ void zero_loss_kernel() {
    if (threadIdx.x < NQ) g_loss[threadIdx.x] = 0.0;
}

__global__ void finalize_loss_kernel(float* out) {
    if (threadIdx.x < NQ)
        out[LOSS_OFF + threadIdx.x] =
            (float)(g_loss[threadIdx.x] * 1.25 / (double)QOUT_ELEMS);
}

// residual = x ; x_n = x / max(||x||, 1e-12)   (one block per token row)
__global__ void init_xr_kernel(const float* __restrict__ x) {
    int row = blockIdx.x;
    int t   = threadIdx.x;                  // 128 threads, 1 float4 each
    const float4* xr = (const float4*)(x + (size_t)row * DIM);
    float4 v = xr[t];
    float s = v.x * v.x + v.y * v.y + v.z * v.z + v.w * v.w;
    s = warp_sum(s);
    __shared__ float ps[4];
    if ((t & 31) == 0) ps[t >> 5] = s;
    __syncthreads();
    float tot = ps[0] + ps[1] + ps[2] + ps[3];
    float inv = 1.0f / fmaxf(sqrtf(tot), 1e-12f);
    ((float4*)(g_res + (size_t)row * DIM))[t] = v;
    float4 n = make_float4(v.x * inv, v.y * inv, v.z * inv, v.w * inv);
    ((float4*)(g_xn + (size_t)row * DIM))[t] = n;
}

// in-place row l2norm of g_cbn (one block per row; NQ*NC rows)
__global__ void cb_norm_kernel() {
    size_t row = blockIdx.x;
    int t = threadIdx.x;
    float4* r = (float4*)(g_cbn + row * DIM);
    float4 v = r[t];
    float s = v.x * v.x + v.y * v.y + v.z * v.z + v.w * v.w;
    s = warp_sum(s);
    __shared__ float ps[4];
    if ((t & 31) == 0) ps[t >> 5] = s;
    __syncthreads();
    float tot = ps[0] + ps[1] + ps[2] + ps[3];
    float inv = 1.0f / fmaxf(sqrtf(tot), 1e-12f);
    r[t] = make_float4(v.x * inv, v.y * inv, v.z * inv, v.w * inv);
}

// ---------------- implicit codebook GEMM --------------------------------------
// cb_raw[s][c][d] = sum_k codebooks[s][c][k] * weights[s][d][k]
// Tile: 64 c-rows x 128 d-cols, 128 threads (16 cols x 8 rows), micro 8x8 via f32x2.
__global__ void __launch_bounds__(128)
cb_gemm_kernel(const float* __restrict__ codebooks, const float* __restrict__ weights) {
    __shared__ __align__(16) float xs[16][64];   // codebook rows, k-major transposed
    __shared__ __align__(16) float cs[16][128];  // weight rows

    int tid = threadIdx.x;
    int row = tid & 7;        // token-group (c dimension)
    int col = tid >> 3;       // code-group (d dimension), 0..15

    int stage = blockIdx.z;
    int m0 = blockIdx.x * 64;     // c base
    int n0 = blockIdx.y * 128;    // d base
    const float* A = codebooks + (size_t)stage * NC * DIM;
    const float* Bm = weights  + (size_t)stage * DIM * DIM;

    ull acc[4][8];
    #pragma unroll
    for (int p = 0; p < 4; p++)
        #pragma unroll
        for (int c = 0; c < 8; c++) acc[p][c] = 0ull;

    for (int kc = 0; kc < 32; kc++) {
        int k0 = kc * 16;
        __syncthreads();
        #pragma unroll
        for (int i = 0; i < 2; i++) {
            int item = tid * 2 + i;
            int tok = item >> 2, k4 = item & 3;
            float4 v = *(const float4*)(A + (size_t)(m0 + tok) * DIM + k0 + k4 * 4);
            xs[k4 * 4 + 0][tok] = v.x; xs[k4 * 4 + 1][tok] = v.y;
            xs[k4 * 4 + 2][tok] = v.z; xs[k4 * 4 + 3][tok] = v.w;
        }
        #pragma unroll
        for (int j = 0; j < 4; j++) {
            int item = j * 128 + tid;
            int code = item >> 2, k4 = item & 3;
            float4 v = *(const float4*)(Bm + (size_t)(n0 + code) * DIM + k0 + k4 * 4);
            cs[k4 * 4 + 0][code] = v.x; cs[k4 * 4 + 1][code] = v.y;
            cs[k4 * 4 + 2][code] = v.z; cs[k4 * 4 + 3][code] = v.w;
        }
        __syncthreads();
        #pragma unroll
        for (int kk = 0; kk < 16; kk++) {
            ull a[4];
            #pragma unroll
            for (int p = 0; p < 4; p++)
                a[p] = *(const ull*)&xs[kk][row * 8 + 2 * p];
            ull b[8];
            #pragma unroll
            for (int c = 0; c < 8; c++) b[c] = dup2(cs[kk][col * 8 + c]);
            #pragma unroll
            for (int p = 0; p < 4; p++)
                #pragma unroll
                for (int c = 0; c < 8; c++) fma2(acc[p][c], a[p], b[c]);
        }
    }

    float* out = g_cbn + (size_t)stage * CBSZ;
    #pragma unroll
    for (int p = 0; p < 4; p++) {
        int cg = m0 + row * 8 + 2 * p;
        #pragma unroll
        for (int c = 0; c < 8; c++) {
            int d = n0 + col * 8 + c;
            out[(size_t)cg * DIM + d]       = lo2(acc[p][c]);
            out[(size_t)(cg + 1) * DIM + d] = hi2(acc[p][c]);
        }
    }
}

// ---------------- fused similarity GEMM + argmax -------------------------------
// For 64 tokens per block, scan all 4096 codes in 128-wide tiles, keep running best.
__global__ void __launch_bounds__(128)
sim_argmax_kernel(int stage) {
    __shared__ __align__(16) float xs[16][64];
    __shared__ __align__(16) float cs[16][128];
    __shared__ float sval[64][17];
    __shared__ int   sidx[64][17];

    int tid = threadIdx.x;
    int row = tid & 7;
    int col = tid >> 3;
    int m0 = blockIdx.x * 64;
    const float* xn = g_xn;
    const float* cb = g_cbn + (size_t)stage * CBSZ;

    float best[8]; int bidx[8];
    #pragma unroll
    for (int i = 0; i < 8; i++) { best[i] = -1e30f; bidx[i] = 0; }

    for (int tile = 0; tile < NC / 128; tile++) {
        int c0 = tile * 128;
        ull acc[4][8];
        #pragma unroll
        for (int p = 0; p < 4; p++)
            #pragma unroll
            for (int c = 0; c < 8; c++) acc[p][c] = 0ull;

        for (int kc = 0; kc < 32; kc++) {
            int k0 = kc * 16;
            __syncthreads();
            #pragma unroll
            for (int i = 0; i < 2; i++) {
                int item = tid * 2 + i;
                int tok = item >> 2, k4 = item & 3;
                float4 v = *(const float4*)(xn + (size_t)(m0 + tok) * DIM + k0 + k4 * 4);
                xs[k4 * 4 + 0][tok] = v.x; xs[k4 * 4 + 1][tok] = v.y;
                xs[k4 * 4 + 2][tok] = v.z; xs[k4 * 4 + 3][tok] = v.w;
            }
            #pragma unroll
            for (int j = 0; j < 4; j++) {
                int item = j * 128 + tid;
                int code = item >> 2, k4 = item & 3;
                float4 v = *(const float4*)(cb + (size_t)(c0 + code) * DIM + k0 + k4 * 4);
                cs[k4 * 4 + 0][code] = v.x; cs[k4 * 4 + 1][code] = v.y;
                cs[k4 * 4 + 2][code] = v.z; cs[k4 * 4 + 3][code] = v.w;
            }
            __syncthreads();
            #pragma unroll
            for (int kk = 0; kk < 16; kk++) {
                ull a[4];
                #pragma unroll
                for (int p = 0; p < 4; p++)
                    a[p] = *(const ull*)&xs[kk][row * 8 + 2 * p];
                ull b[8];
                #pragma unroll
                for (int c = 0; c < 8; c++) b[c] = dup2(cs[kk][col * 8 + c]);
                #pragma unroll
                for (int p = 0; p < 4; p++)
                    #pragma unroll
                    for (int c = 0; c < 8; c++) fma2(acc[p][c], a[p], b[c]);
            }
        }
        // update running argmax (codes ascending within thread)
        #pragma unroll
        for (int p = 0; p < 4; p++)
            #pragma unroll
            for (int c = 0; c < 8; c++) {
                int code = c0 + col * 8 + c;
                float s0 = lo2(acc[p][c]);
                float s1 = hi2(acc[p][c]);
                if (s0 > best[2 * p])     { best[2 * p] = s0;     bidx[2 * p] = code; }
                if (s1 > best[2 * p + 1]) { best[2 * p + 1] = s1; bidx[2 * p + 1] = code; }
            }
    }

    __syncthreads();
    #pragma unroll
    for (int lt = 0; lt < 8; lt++) {
        sval[row * 8 + lt][col] = best[lt];
        sidx[row * 8 + lt][col] = bidx[lt];
    }
    __syncthreads();
    if (tid < 64) {
        float bv = -1e30f; int bi = NC;
        #pragma unroll
        for (int c = 0; c < 16; c++) {
            float v = sval[tid][c]; int i = sidx[tid][c];
            if (v > bv || (v == bv && i < bi)) { bv = v; bi = i; }
        }
        g_idx[m0 + tid] = bi;
    }
}

// ---------------- rotation-trick update per token ------------------------------
// out = ax*x_n + aq*quant ; residual -= out ; quantized_out += out ; next x_n.
__global__ void rotate_update_kernel(int stage, float* __restrict__ out, int write_aux) {
    int warp = threadIdx.x >> 5;
    int lane = threadIdx.x & 31;
    int token = blockIdx.x * 8 + warp;

    const float4* xr = (const float4*)(g_xn + (size_t)token * DIM);
    float4*       rr = (float4*)(g_res + (size_t)token * DIM);
    int code = g_idx[token];
    const float4* qr = (const float4*)(g_cbn + (size_t)stage * CBSZ + (size_t)code * DIM);

    float4 xv[4], qv[4];
    float see = 0.f, stt = 0.f, set = 0.f;
    #pragma unroll
    for (int j = 0; j < 4; j++) {
        xv[j] = xr[lane + j * 32];
        qv[j] = qr[lane + j * 32];
        see += xv[j].x * xv[j].x + xv[j].y * xv[j].y + xv[j].z * xv[j].z + xv[j].w * xv[j].w;
        stt += qv[j].x * qv[j].x + qv[j].y * qv[j].y + qv[j].z * qv[j].z + qv[j].w * qv[j].w;
        set += xv[j].x * qv[j].x + xv[j].y * qv[j].y + xv[j].z * qv[j].z + xv[j].w * qv[j].w;
    }
    see = warp_sum(see); stt = warp_sum(stt); set = warp_sum(set);

    float ns = sqrtf(see), nt = sqrtf(stt);
    float eu = see / ns;
    float eq = set / nt;
    float nw2 = 2.f + 2.f * set / (ns * nt);
    float nw = fmaxf(sqrtf(nw2), 1e-12f);
    float cw = 2.f * (eu + eq) / (nw * nw);
    float ax = (nt / ns) * (1.f - cw / ns);
    float aq = (2.f * eu - cw) / ns;
    float scc = see - 2.f * set + stt;       // sum((x_n - quant)^2)

    float4* qo = (float4*)(out + (size_t)token * DIM);
    float rn2 = 0.f;
    float4 rnv[4];
    #pragma unroll
    for (int j = 0; j < 4; j++) {
        float4 o;
        o.x = ax * xv[j].x + aq * qv[j].x;
        o.y = ax * xv[j].y + aq * qv[j].y;
        o.z = ax * xv[j].z + aq * qv[j].z;
        o.w = ax * xv[j].w + aq * qv[j].w;
        float4 r = rr[lane + j * 32];
        if (stage == 0) {
            qo[lane + j * 32] = o;
        } else {
            float4 prev = qo[lane + j * 32];
            prev.x += o.x; prev.y += o.y; prev.z += o.z; prev.w += o.w;
            qo[lane + j * 32] = prev;
        }
        float4 rn;
        rn.x = r.x - o.x; rn.y = r.y - o.y; rn.z = r.z - o.z; rn.w = r.w - o.w;
        rr[lane + j * 32] = rn;
        rnv[j] = rn;
        rn2 += rn.x * rn.x + rn.y * rn.y + rn.z * rn.z + rn.w * rn.w;
    }
    if (stage < NQ - 1) {
        rn2 = warp_sum(rn2);
        float inv = 1.f / fmaxf(sqrtf(rn2), 1e-12f);
        float4* xw = (float4*)(g_xn + (size_t)token * DIM);
        #pragma unroll
        for (int j = 0; j < 4; j++) {
            float4 n = make_float4(rnv[j].x * inv, rnv[j].y * inv,
                                   rnv[j].z * inv, rnv[j].w * inv);
            xw[lane + j * 32] = n;
        }
    }
    if (lane == 0 && write_aux)
        out[IDX_OFF + (size_t)token * NQ + stage] = (float)code;

    // loss accumulation (block-level, then one double atomic)
    __shared__ float wscc[8];
    if (lane == 0) wscc[warp] = scc;
    __syncthreads();
    if (threadIdx.x == 0) {
        float s = 0.f;
        #pragma unroll
        for (int w = 0; w < 8; w++) s += wscc[w];
        atomicAdd(&g_loss[stage], (double)s);
    }
}

// ---------------- launch ------------------------------------------------------
extern "C" void kernel_launch(void* const* d_in, const int* in_sizes, int n_in,
                              void* d_out, int out_size) {
    const float* x         = (const float*)d_in[0];
    const float* codebooks = (const float*)d_in[1];
    const float* weights   = (const float*)d_in[2];
    float* out = (float*)d_out;
    int write_aux = (out_size >= OUT_FULL) ? 1 : 0;

    zero_loss_kernel<<<1, 32>>>();
    cb_gemm_kernel<<<dim3(NC / 64, DIM / 128, NQ), 128>>>(codebooks, weights);
    cb_norm_kernel<<<NQ * NC, 128>>>();
    init_xr_kernel<<<BN, 128>>>(x);
    for (int s = 0; s < NQ; s++) {
        sim_argmax_kernel<<<BN / 64, 128>>>(s);
        rotate_update_kernel<<<BN / 8, 256>>>(s, out, write_aux);
    }
    if (write_aux) finalize_loss_kernel<<<1, 32>>>(out);
}

// round 6
// speedup vs baseline: 1.6956x; 1.6956x over previous
#include <cuda_runtime.h>
#include <cuda_bf16.h>
#include <math.h>
#include <stdint.h>

// Problem constants
#define BN     16384           // B*N tokens
#define DIM    512
#define NC     4096            // codes per stage
#define NQ     4               // stages
#define CBSZ   (NC * DIM)      // floats per stage codebook
#define QOUT_ELEMS  (BN * DIM)               // 8388608
#define IDX_OFF     QOUT_ELEMS
#define IDX_ELEMS   (BN * NQ)                // 65536
#define LOSS_OFF    (IDX_OFF + IDX_ELEMS)
#define OUT_FULL    (LOSS_OFF + NQ)

typedef unsigned long long ull;

// ---------------- device scratch (static globals; no runtime alloc) ----------
__device__ float  g_cbn[(size_t)NQ * CBSZ];     // normalized implicit codebooks (32MB)
__device__ float  g_xn [(size_t)BN * DIM];      // l2norm(residual) (32MB)
__device__ float  g_res[(size_t)BN * DIM];      // residual (32MB)
__device__ int    g_idx[BN];
__device__ double g_loss[NQ];

// ---------------- helpers ------------------------------------------------------
__device__ __forceinline__ uint32_t smem_to_u32(const void* p) {
    uint32_t a;
    asm("{ .reg .u64 t; cvta.to.shared.u64 t, %1; cvt.u32.u64 %0, t; }" : "=r"(a) : "l"(p));
    return a;
}
__device__ __forceinline__ float warp_sum(float v) {
    #pragma unroll
    for (int o = 16; o; o >>= 1) v += __shfl_xor_sync(0xffffffffu, v, o);
    return v;
}
__device__ __forceinline__ uint32_t tf32r(float x) {
    uint32_t r; asm("cvt.rna.tf32.f32 %0, %1;" : "=r"(r) : "f"(x)); return r;
}
__device__ __forceinline__ ull dup2(float x) {
    ull r; asm("mov.b64 %0, {%1, %1};" : "=l"(r) : "f"(x)); return r;
}
__device__ __forceinline__ void fma2(ull& a, ull x, ull y) {
    asm("fma.rn.f32x2 %0, %1, %2, %0;" : "+l"(a) : "l"(x), "l"(y));
}
__device__ __forceinline__ float lo2(ull a) { return __uint_as_float((unsigned)a); }
__device__ __forceinline__ float hi2(ull a) { return __uint_as_float((unsigned)(a >> 32)); }

// ldmatrix / mma (baseline PTX ISA — valid for plain sm_103 target)
__device__ __forceinline__ void ldm_x4(uint32_t* r, uint32_t addr) {
    asm volatile("ldmatrix.sync.aligned.m8n8.x4.shared.b16 {%0,%1,%2,%3}, [%4];"
        : "=r"(r[0]), "=r"(r[1]), "=r"(r[2]), "=r"(r[3]) : "r"(addr));
}
__device__ __forceinline__ void mma_tf32(float* d, const uint32_t* a, const uint32_t* b) {
    asm volatile(
        "mma.sync.aligned.m16n8k8.row.col.f32.tf32.tf32.f32 "
        "{%0,%1,%2,%3}, {%4,%5,%6,%7}, {%8,%9}, {%0,%1,%2,%3};"
        : "+f"(d[0]), "+f"(d[1]), "+f"(d[2]), "+f"(d[3])
        : "r"(a[0]), "r"(a[1]), "r"(a[2]), "r"(a[3]), "r"(b[0]), "r"(b[1]));
}

#define SWZ(off) ((off) ^ (((off) >> 3) & 0x70u))

// ---------------- misc small kernels -----------------------------------------
__global__ void zero_loss_kernel() {
    if (threadIdx.x < NQ) g_loss[threadIdx.x] = 0.0;
}

__global__ void finalize_loss_kernel(float* out) {
    if (threadIdx.x < NQ)
        out[LOSS_OFF + threadIdx.x] =
            (float)(g_loss[threadIdx.x] * 1.25 / (double)QOUT_ELEMS);
}

// residual = x ; x_n = x / max(||x||, 1e-12)   (one block per token row)
__global__ void init_xr_kernel(const float* __restrict__ x) {
    int row = blockIdx.x;
    int t   = threadIdx.x;
    const float4* xr = (const float4*)(x + (size_t)row * DIM);
    float4 v = xr[t];
    float s = v.x * v.x + v.y * v.y + v.z * v.z + v.w * v.w;
    s = warp_sum(s);
    __shared__ float ps[4];
    if ((t & 31) == 0) ps[t >> 5] = s;
    __syncthreads();
    float tot = ps[0] + ps[1] + ps[2] + ps[3];
    float inv = 1.0f / fmaxf(sqrtf(tot), 1e-12f);
    ((float4*)(g_res + (size_t)row * DIM))[t] = v;
    float4 n = make_float4(v.x * inv, v.y * inv, v.z * inv, v.w * inv);
    ((float4*)(g_xn + (size_t)row * DIM))[t] = n;
}

// in-place row l2norm of g_cbn (one block per row; NQ*NC rows)
__global__ void cb_norm_kernel() {
    size_t row = blockIdx.x;
    int t = threadIdx.x;
    float4* r = (float4*)(g_cbn + row * DIM);
    float4 v = r[t];
    float s = v.x * v.x + v.y * v.y + v.z * v.z + v.w * v.w;
    s = warp_sum(s);
    __shared__ float ps[4];
    if ((t & 31) == 0) ps[t >> 5] = s;
    __syncthreads();
    float tot = ps[0] + ps[1] + ps[2] + ps[3];
    float inv = 1.0f / fmaxf(sqrtf(tot), 1e-12f);
    r[t] = make_float4(v.x * inv, v.y * inv, v.z * inv, v.w * inv);
}

// ---------------- implicit codebook GEMM (FFMA2) ------------------------------
__global__ void __launch_bounds__(128)
cb_gemm_kernel(const float* __restrict__ codebooks, const float* __restrict__ weights) {
    __shared__ __align__(16) float xs[16][64];
    __shared__ __align__(16) float cs[16][128];

    int tid = threadIdx.x;
    int row = tid & 7;
    int col = tid >> 3;

    int stage = blockIdx.z;
    int m0 = blockIdx.x * 64;
    int n0 = blockIdx.y * 128;
    const float* A = codebooks + (size_t)stage * NC * DIM;
    const float* Bm = weights  + (size_t)stage * DIM * DIM;

    ull acc[4][8];
    #pragma unroll
    for (int p = 0; p < 4; p++)
        #pragma unroll
        for (int c = 0; c < 8; c++) acc[p][c] = 0ull;

    for (int kc = 0; kc < 32; kc++) {
        int k0 = kc * 16;
        __syncthreads();
        #pragma unroll
        for (int i = 0; i < 2; i++) {
            int item = tid * 2 + i;
            int tok = item >> 2, k4 = item & 3;
            float4 v = *(const float4*)(A + (size_t)(m0 + tok) * DIM + k0 + k4 * 4);
            xs[k4 * 4 + 0][tok] = v.x; xs[k4 * 4 + 1][tok] = v.y;
            xs[k4 * 4 + 2][tok] = v.z; xs[k4 * 4 + 3][tok] = v.w;
        }
        #pragma unroll
        for (int j = 0; j < 4; j++) {
            int item = j * 128 + tid;
            int code = item >> 2, k4 = item & 3;
            float4 v = *(const float4*)(Bm + (size_t)(n0 + code) * DIM + k0 + k4 * 4);
            cs[k4 * 4 + 0][code] = v.x; cs[k4 * 4 + 1][code] = v.y;
            cs[k4 * 4 + 2][code] = v.z; cs[k4 * 4 + 3][code] = v.w;
        }
        __syncthreads();
        #pragma unroll
        for (int kk = 0; kk < 16; kk++) {
            ull a[4];
            #pragma unroll
            for (int p = 0; p < 4; p++)
                a[p] = *(const ull*)&xs[kk][row * 8 + 2 * p];
            ull b[8];
            #pragma unroll
            for (int c = 0; c < 8; c++) b[c] = dup2(cs[kk][col * 8 + c]);
            #pragma unroll
            for (int p = 0; p < 4; p++)
                #pragma unroll
                for (int c = 0; c < 8; c++) fma2(acc[p][c], a[p], b[c]);
        }
    }

    float* out = g_cbn + (size_t)stage * CBSZ;
    #pragma unroll
    for (int p = 0; p < 4; p++) {
        int cg = m0 + row * 8 + 2 * p;
        #pragma unroll
        for (int c = 0; c < 8; c++) {
            int d = n0 + col * 8 + c;
            out[(size_t)cg * DIM + d]       = lo2(acc[p][c]);
            out[(size_t)(cg + 1) * DIM + d] = hi2(acc[p][c]);
        }
    }
}

// ================== mma.sync tf32-split sim + fused argmax =====================
// Block: 256 thr (8 warps, 4 M-warps x 2 N-warps). Block tile 128 tok x 128 codes,
// looped over 32 code tiles. K staged in double-buffered 32-dim chunks, fp32 ->
// tf32 hi/lo split on the fly. sim = Xh*Ch + Xh*Cl + Xl*Ch (fp32 accum).
#define XH_O 0
#define XL_O 16384
#define CH_O 32768
#define CL_O 49152
#define BUFSZ 65536
#define SMEM_MMA (2 * BUFSZ)      // 128KB dynamic
#define NTILES 32
#define KCHUNKS 16                // 512 / 32

__device__ __forceinline__ void cvt_store(char* hb, char* lb, uint32_t sw, float4 v) {
    uint32_t h0 = tf32r(v.x), h1 = tf32r(v.y), h2 = tf32r(v.z), h3 = tf32r(v.w);
    uint4 hv = make_uint4(h0, h1, h2, h3);
    uint4 lv = make_uint4(tf32r(v.x - __uint_as_float(h0)),
                          tf32r(v.y - __uint_as_float(h1)),
                          tf32r(v.z - __uint_as_float(h2)),
                          tf32r(v.w - __uint_as_float(h3)));
    *(uint4*)(hb + sw) = hv;
    *(uint4*)(lb + sw) = lv;
}

__global__ void __launch_bounds__(256, 1)
sim_mma_kernel(int stage) {
    extern __shared__ __align__(16) char smem[];
    uint32_t sb = smem_to_u32(smem);

    int tid  = threadIdx.x;
    int lane = tid & 31;
    int warp = tid >> 5;
    int wm = warp & 3;            // 0..3  -> m offset wm*32
    int wn = warp >> 2;           // 0..1  -> n offset wn*64

    int m0 = blockIdx.x * 128;
    const float* xn = g_xn + (size_t)m0 * DIM;
    const float* cb = g_cbn + (size_t)stage * CBSZ;

    // staging indices (4 items per thread per 128x32 matrix)
    int srow[4], sslot[4];
    uint32_t ssw[4];
    #pragma unroll
    for (int it = 0; it < 4; it++) {
        int item = it * 256 + tid;
        srow[it]  = item >> 3;
        sslot[it] = item & 7;
        uint32_t off = (uint32_t)srow[it] * 128u + (uint32_t)sslot[it] * 16u;
        ssw[it] = SWZ(off);
    }

    // ldmatrix per-lane swizzled offsets (within a 128x(32tf32) matrix)
    // A frags: row = wm*32 + mf*16 + (lane&15), bytecol = ks*32 + ((lane>>4)<<4)
    // B frags: row = wn*64 + nf2*16 + ((lane>>4)<<3) + (lane&7),
    //          bytecol = ks*32 + (((lane>>3)&1)<<4)
    int a_r = wm * 32 + (lane & 15);
    int a_c = (lane >> 4) << 4;
    int b_r = wn * 64 + ((lane >> 4) << 3) + (lane & 7);
    int b_c = ((lane >> 3) & 1) << 4;

    float best[4]; int bidx[4];
    #pragma unroll
    for (int s = 0; s < 4; s++) { best[s] = -1e30f; bidx[s] = 0; }

    for (int nt = 0; nt < NTILES; nt++) {
        const float* cbt = cb + (size_t)(nt * 128) * DIM;

        float acc[2][8][4];
        #pragma unroll
        for (int mf = 0; mf < 2; mf++)
            #pragma unroll
            for (int nf = 0; nf < 8; nf++)
                #pragma unroll
                for (int q = 0; q < 4; q++) acc[mf][nf][q] = 0.f;

        // prefetch chunk 0
        float4 xv[4], cv[4];
        #pragma unroll
        for (int it = 0; it < 4; it++) {
            xv[it] = *(const float4*)(xn  + (size_t)srow[it] * DIM + sslot[it] * 4);
            cv[it] = *(const float4*)(cbt + (size_t)srow[it] * DIM + sslot[it] * 4);
        }
        #pragma unroll
        for (int it = 0; it < 4; it++) {
            cvt_store(smem + XH_O, smem + XL_O, ssw[it], xv[it]);
            cvt_store(smem + CH_O, smem + CL_O, ssw[it], cv[it]);
        }
        __syncthreads();

        for (int g = 0; g < KCHUNKS; g++) {
            // issue global loads for chunk g+1 (hide behind mma)
            if (g + 1 < KCHUNKS) {
                int k0 = (g + 1) * 32;
                #pragma unroll
                for (int it = 0; it < 4; it++) {
                    xv[it] = *(const float4*)(xn  + (size_t)srow[it] * DIM + k0 + sslot[it] * 4);
                    cv[it] = *(const float4*)(cbt + (size_t)srow[it] * DIM + k0 + sslot[it] * 4);
                }
            }
            // compute on buf[g&1]
            uint32_t bufb = sb + (uint32_t)((g & 1) * BUFSZ);
            #pragma unroll
            for (int ks = 0; ks < 4; ks++) {
                uint32_t ah[2][4], al[2][4];
                #pragma unroll
                for (int mf = 0; mf < 2; mf++) {
                    uint32_t off = (uint32_t)(a_r + mf * 16) * 128u + (uint32_t)(ks * 32 + a_c);
                    uint32_t sw = SWZ(off);
                    ldm_x4(ah[mf], bufb + XH_O + sw);
                    ldm_x4(al[mf], bufb + XL_O + sw);
                }
                uint32_t bh[16], bl[16];
                #pragma unroll
                for (int nf2 = 0; nf2 < 4; nf2++) {
                    uint32_t off = (uint32_t)(b_r + nf2 * 16) * 128u + (uint32_t)(ks * 32 + b_c);
                    uint32_t sw = SWZ(off);
                    ldm_x4(&bh[nf2 * 4], bufb + CH_O + sw);
                    ldm_x4(&bl[nf2 * 4], bufb + CL_O + sw);
                }
                #pragma unroll
                for (int mf = 0; mf < 2; mf++)
                    #pragma unroll
                    for (int nf = 0; nf < 8; nf++) {
                        mma_tf32(acc[mf][nf], ah[mf], &bh[nf * 2]);
                        mma_tf32(acc[mf][nf], ah[mf], &bl[nf * 2]);
                        mma_tf32(acc[mf][nf], al[mf], &bh[nf * 2]);
                    }
            }
            // store chunk g+1 into the other buffer
            if (g + 1 < KCHUNKS) {
                char* nb = smem + ((g + 1) & 1) * BUFSZ;
                #pragma unroll
                for (int it = 0; it < 4; it++) {
                    cvt_store(nb + XH_O, nb + XL_O, ssw[it], xv[it]);
                    cvt_store(nb + CH_O, nb + CL_O, ssw[it], cv[it]);
                }
            }
            __syncthreads();
        }

        // fused argmax: thread owns rows (wm*32 + mf*16 + lane/4 [+8]), cols known
        int cb0 = nt * 128 + wn * 64 + (lane & 3) * 2;
        #pragma unroll
        for (int mf = 0; mf < 2; mf++)
            #pragma unroll
            for (int nf = 0; nf < 8; nf++) {
                int c = cb0 + nf * 8;
                float v0 = acc[mf][nf][0], v1 = acc[mf][nf][1];
                float v2 = acc[mf][nf][2], v3 = acc[mf][nf][3];
                int s0 = mf * 2, s1 = mf * 2 + 1;
                if (v0 > best[s0]) { best[s0] = v0; bidx[s0] = c; }
                if (v1 > best[s0]) { best[s0] = v1; bidx[s0] = c + 1; }
                if (v2 > best[s1]) { best[s1] = v2; bidx[s1] = c; }
                if (v3 > best[s1]) { best[s1] = v3; bidx[s1] = c + 1; }
            }
    }

    // reduce across the 4 lanes sharing each row (lane%4 varies)
    #pragma unroll
    for (int s = 0; s < 4; s++) {
        #pragma unroll
        for (int off = 1; off <= 2; off <<= 1) {
            float ov = __shfl_xor_sync(0xffffffffu, best[s], off);
            int   oi = __shfl_xor_sync(0xffffffffu, bidx[s], off);
            if (ov > best[s] || (ov == best[s] && oi < bidx[s])) {
                best[s] = ov; bidx[s] = oi;
            }
        }
    }
    __syncthreads();   // done with mma buffers; reuse smem for reduction
    float* sval = (float*)smem;              // [128][2]
    int*   sidx = (int*)(smem + 128 * 2 * 4);
    if ((lane & 3) == 0) {
        #pragma unroll
        for (int s = 0; s < 4; s++) {
            int row = wm * 32 + (s >> 1) * 16 + (lane >> 2) + (s & 1) * 8;
            sval[row * 2 + wn] = best[s];
            sidx[row * 2 + wn] = bidx[s];
        }
    }
    __syncthreads();
    if (tid < 128) {
        float v0 = sval[tid * 2], v1 = sval[tid * 2 + 1];
        int   i0 = sidx[tid * 2], i1 = sidx[tid * 2 + 1];
        int bi = (v1 > v0 || (v1 == v0 && i1 < i0)) ? i1 : i0;
        g_idx[m0 + tid] = bi;
    }
}

// ---------------- rotation-trick update per token ------------------------------
__global__ void rotate_update_kernel(int stage, float* __restrict__ out, int write_aux) {
    int warp = threadIdx.x >> 5;
    int lane = threadIdx.x & 31;
    int token = blockIdx.x * 8 + warp;

    const float4* xr = (const float4*)(g_xn + (size_t)token * DIM);
    float4*       rr = (float4*)(g_res + (size_t)token * DIM);
    int code = g_idx[token];
    const float4* qr = (const float4*)(g_cbn + (size_t)stage * CBSZ + (size_t)code * DIM);

    float4 xv[4], qv[4];
    float see = 0.f, stt = 0.f, set = 0.f;
    #pragma unroll
    for (int j = 0; j < 4; j++) {
        xv[j] = xr[lane + j * 32];
        qv[j] = qr[lane + j * 32];
        see += xv[j].x * xv[j].x + xv[j].y * xv[j].y + xv[j].z * xv[j].z + xv[j].w * xv[j].w;
        stt += qv[j].x * qv[j].x + qv[j].y * qv[j].y + qv[j].z * qv[j].z + qv[j].w * qv[j].w;
        set += xv[j].x * qv[j].x + xv[j].y * qv[j].y + xv[j].z * qv[j].z + xv[j].w * qv[j].w;
    }
    see = warp_sum(see); stt = warp_sum(stt); set = warp_sum(set);

    float ns = sqrtf(see), nt = sqrtf(stt);
    float eu = see / ns;
    float eq = set / nt;
    float nw2 = 2.f + 2.f * set / (ns * nt);
    float nw = fmaxf(sqrtf(nw2), 1e-12f);
    float cw = 2.f * (eu + eq) / (nw * nw);
    float ax = (nt / ns) * (1.f - cw / ns);
    float aq = (2.f * eu - cw) / ns;
    float scc = see - 2.f * set + stt;

    float4* qo = (float4*)(out + (size_t)token * DIM);
    float rn2 = 0.f;
    float4 rnv[4];
    #pragma unroll
    for (int j = 0; j < 4; j++) {
        float4 o;
        o.x = ax * xv[j].x + aq * qv[j].x;
        o.y = ax * xv[j].y + aq * qv[j].y;
        o.z = ax * xv[j].z + aq * qv[j].z;
        o.w = ax * xv[j].w + aq * qv[j].w;
        float4 r = rr[lane + j * 32];
        if (stage == 0) {
            qo[lane + j * 32] = o;
        } else {
            float4 prev = qo[lane + j * 32];
            prev.x += o.x; prev.y += o.y; prev.z += o.z; prev.w += o.w;
            qo[lane + j * 32] = prev;
        }
        float4 rn;
        rn.x = r.x - o.x; rn.y = r.y - o.y; rn.z = r.z - o.z; rn.w = r.w - o.w;
        rr[lane + j * 32] = rn;
        rnv[j] = rn;
        rn2 += rn.x * rn.x + rn.y * rn.y + rn.z * rn.z + rn.w * rn.w;
    }
    if (stage < NQ - 1) {
        rn2 = warp_sum(rn2);
        float inv = 1.f / fmaxf(sqrtf(rn2), 1e-12f);
        float4* xw = (float4*)(g_xn + (size_t)token * DIM);
        #pragma unroll
        for (int j = 0; j < 4; j++) {
            float4 n = make_float4(rnv[j].x * inv, rnv[j].y * inv,
                                   rnv[j].z * inv, rnv[j].w * inv);
            xw[lane + j * 32] = n;
        }
    }
    if (lane == 0 && write_aux)
        out[IDX_OFF + (size_t)token * NQ + stage] = (float)code;

    __shared__ float wscc[8];
    if (lane == 0) wscc[warp] = scc;
    __syncthreads();
    if (threadIdx.x == 0) {
        float s = 0.f;
        #pragma unroll
        for (int w = 0; w < 8; w++) s += wscc[w];
        atomicAdd(&g_loss[stage], (double)s);
    }
}

// ---------------- launch ------------------------------------------------------
extern "C" void kernel_launch(void* const* d_in, const int* in_sizes, int n_in,
                              void* d_out, int out_size) {
    const float* x         = (const float*)d_in[0];
    const float* codebooks = (const float*)d_in[1];
    const float* weights   = (const float*)d_in[2];
    float* out = (float*)d_out;
    int write_aux = (out_size >= OUT_FULL) ? 1 : 0;

    cudaFuncSetAttribute(sim_mma_kernel,
                         cudaFuncAttributeMaxDynamicSharedMemorySize, SMEM_MMA);

    zero_loss_kernel<<<1, 32>>>();
    cb_gemm_kernel<<<dim3(NC / 64, DIM / 128, NQ), 128>>>(codebooks, weights);
    cb_norm_kernel<<<NQ * NC, 128>>>();
    init_xr_kernel<<<BN, 128>>>(x);
    for (int s = 0; s < NQ; s++) {
        sim_mma_kernel<<<BN / 128, 256, SMEM_MMA>>>(s);
        rotate_update_kernel<<<BN / 8, 256>>>(s, out, write_aux);
    }
    if (write_aux) finalize_loss_kernel<<<1, 32>>>(out);
}

// round 7
// speedup vs baseline: 2.9033x; 1.7123x over previous
#include <cuda_runtime.h>
#include <cuda_bf16.h>
#include <math.h>
#include <stdint.h>

// Problem constants
#define BN     16384           // B*N tokens
#define DIM    512
#define NC     4096            // codes per stage
#define NQ     4               // stages
#define CBSZ   (NC * DIM)      // floats per stage codebook
#define QOUT_ELEMS  (BN * DIM)               // 8388608
#define IDX_OFF     QOUT_ELEMS
#define IDX_ELEMS   (BN * NQ)                // 65536
#define LOSS_OFF    (IDX_OFF + IDX_ELEMS)
#define OUT_FULL    (LOSS_OFF + NQ)

typedef unsigned long long ull;

// ---------------- device scratch (static globals; no runtime alloc) ----------
__device__ float  g_cbn[(size_t)NQ * CBSZ];     // normalized implicit codebooks (32MB)
__device__ float  g_xn [(size_t)BN * DIM];      // l2norm(residual) (32MB)
__device__ float  g_res[(size_t)BN * DIM];      // residual (32MB)
__device__ int    g_idx[BN];
__device__ double g_loss[NQ];

// ---------------- helpers ------------------------------------------------------
__device__ __forceinline__ uint32_t smem_to_u32(const void* p) {
    uint32_t a;
    asm("{ .reg .u64 t; cvta.to.shared.u64 t, %1; cvt.u32.u64 %0, t; }" : "=r"(a) : "l"(p));
    return a;
}
__device__ __forceinline__ float warp_sum(float v) {
    #pragma unroll
    for (int o = 16; o; o >>= 1) v += __shfl_xor_sync(0xffffffffu, v, o);
    return v;
}
__device__ __forceinline__ ull dup2(float x) {
    ull r; asm("mov.b64 %0, {%1, %1};" : "=l"(r) : "f"(x)); return r;
}
__device__ __forceinline__ void fma2(ull& a, ull x, ull y) {
    asm("fma.rn.f32x2 %0, %1, %2, %0;" : "+l"(a) : "l"(x), "l"(y));
}
__device__ __forceinline__ float lo2(ull a) { return __uint_as_float((unsigned)a); }
__device__ __forceinline__ float hi2(ull a) { return __uint_as_float((unsigned)(a >> 32)); }

// ldmatrix / mma (baseline PTX ISA — valid for plain sm_103 target)
__device__ __forceinline__ void ldm_x4(uint32_t* r, uint32_t addr) {
    asm volatile("ldmatrix.sync.aligned.m8n8.x4.shared.b16 {%0,%1,%2,%3}, [%4];"
        : "=r"(r[0]), "=r"(r[1]), "=r"(r[2]), "=r"(r[3]) : "r"(addr));
}
__device__ __forceinline__ void mma_bf16(float* d, const uint32_t* a, const uint32_t* b) {
    asm volatile(
        "mma.sync.aligned.m16n8k16.row.col.f32.bf16.bf16.f32 "
        "{%0,%1,%2,%3}, {%4,%5,%6,%7}, {%8,%9}, {%0,%1,%2,%3};"
        : "+f"(d[0]), "+f"(d[1]), "+f"(d[2]), "+f"(d[3])
        : "r"(a[0]), "r"(a[1]), "r"(a[2]), "r"(a[3]), "r"(b[0]), "r"(b[1]));
}

#define SWZ(off) ((off) ^ (((off) >> 3) & 0x70u))

// bf16 split-2 packing: hi = bf16(x), lo = bf16(x - hi); pack pairs (lo half = first elem)
__device__ __forceinline__ uint32_t pack_bf16(float e0, float e1) {
    uint32_t r; asm("cvt.rn.bf16x2.f32 %0, %1, %2;" : "=r"(r) : "f"(e1), "f"(e0)); return r;
}
__device__ __forceinline__ float bflo(uint32_t p) { return __uint_as_float(p << 16); }
__device__ __forceinline__ float bfhi(uint32_t p) { return __uint_as_float(p & 0xffff0000u); }

__device__ __forceinline__ void cvt_store8(char* hb, char* lb, uint32_t sw,
                                           float4 a, float4 b) {
    uint4 hv, lv;
    hv.x = pack_bf16(a.x, a.y); hv.y = pack_bf16(a.z, a.w);
    hv.z = pack_bf16(b.x, b.y); hv.w = pack_bf16(b.z, b.w);
    lv.x = pack_bf16(a.x - bflo(hv.x), a.y - bfhi(hv.x));
    lv.y = pack_bf16(a.z - bflo(hv.y), a.w - bfhi(hv.y));
    lv.z = pack_bf16(b.x - bflo(hv.z), b.y - bfhi(hv.z));
    lv.w = pack_bf16(b.z - bflo(hv.w), b.w - bfhi(hv.w));
    *(uint4*)(hb + sw) = hv;
    *(uint4*)(lb + sw) = lv;
}

// ---------------- misc small kernels -----------------------------------------
__global__ void zero_loss_kernel() {
    if (threadIdx.x < NQ) g_loss[threadIdx.x] = 0.0;
}

__global__ void finalize_loss_kernel(float* out) {
    if (threadIdx.x < NQ)
        out[LOSS_OFF + threadIdx.x] =
            (float)(g_loss[threadIdx.x] * 1.25 / (double)QOUT_ELEMS);
}

// residual = x ; x_n = x / max(||x||, 1e-12)   (one block per token row)
__global__ void init_xr_kernel(const float* __restrict__ x) {
    int row = blockIdx.x;
    int t   = threadIdx.x;
    const float4* xr = (const float4*)(x + (size_t)row * DIM);
    float4 v = xr[t];
    float s = v.x * v.x + v.y * v.y + v.z * v.z + v.w * v.w;
    s = warp_sum(s);
    __shared__ float ps[4];
    if ((t & 31) == 0) ps[t >> 5] = s;
    __syncthreads();
    float tot = ps[0] + ps[1] + ps[2] + ps[3];
    float inv = 1.0f / fmaxf(sqrtf(tot), 1e-12f);
    ((float4*)(g_res + (size_t)row * DIM))[t] = v;
    float4 n = make_float4(v.x * inv, v.y * inv, v.z * inv, v.w * inv);
    ((float4*)(g_xn + (size_t)row * DIM))[t] = n;
}

// in-place row l2norm of g_cbn (one block per row; NQ*NC rows)
__global__ void cb_norm_kernel() {
    size_t row = blockIdx.x;
    int t = threadIdx.x;
    float4* r = (float4*)(g_cbn + row * DIM);
    float4 v = r[t];
    float s = v.x * v.x + v.y * v.y + v.z * v.z + v.w * v.w;
    s = warp_sum(s);
    __shared__ float ps[4];
    if ((t & 31) == 0) ps[t >> 5] = s;
    __syncthreads();
    float tot = ps[0] + ps[1] + ps[2] + ps[3];
    float inv = 1.0f / fmaxf(sqrtf(tot), 1e-12f);
    r[t] = make_float4(v.x * inv, v.y * inv, v.z * inv, v.w * inv);
}

// ---------------- implicit codebook GEMM (FFMA2) ------------------------------
__global__ void __launch_bounds__(128)
cb_gemm_kernel(const float* __restrict__ codebooks, const float* __restrict__ weights) {
    __shared__ __align__(16) float xs[16][64];
    __shared__ __align__(16) float cs[16][128];

    int tid = threadIdx.x;
    int row = tid & 7;
    int col = tid >> 3;

    int stage = blockIdx.z;
    int m0 = blockIdx.x * 64;
    int n0 = blockIdx.y * 128;
    const float* A = codebooks + (size_t)stage * NC * DIM;
    const float* Bm = weights  + (size_t)stage * DIM * DIM;

    ull acc[4][8];
    #pragma unroll
    for (int p = 0; p < 4; p++)
        #pragma unroll
        for (int c = 0; c < 8; c++) acc[p][c] = 0ull;

    for (int kc = 0; kc < 32; kc++) {
        int k0 = kc * 16;
        __syncthreads();
        #pragma unroll
        for (int i = 0; i < 2; i++) {
            int item = tid * 2 + i;
            int tok = item >> 2, k4 = item & 3;
            float4 v = *(const float4*)(A + (size_t)(m0 + tok) * DIM + k0 + k4 * 4);
            xs[k4 * 4 + 0][tok] = v.x; xs[k4 * 4 + 1][tok] = v.y;
            xs[k4 * 4 + 2][tok] = v.z; xs[k4 * 4 + 3][tok] = v.w;
        }
        #pragma unroll
        for (int j = 0; j < 4; j++) {
            int item = j * 128 + tid;
            int code = item >> 2, k4 = item & 3;
            float4 v = *(const float4*)(Bm + (size_t)(n0 + code) * DIM + k0 + k4 * 4);
            cs[k4 * 4 + 0][code] = v.x; cs[k4 * 4 + 1][code] = v.y;
            cs[k4 * 4 + 2][code] = v.z; cs[k4 * 4 + 3][code] = v.w;
        }
        __syncthreads();
        #pragma unroll
        for (int kk = 0; kk < 16; kk++) {
            ull a[4];
            #pragma unroll
            for (int p = 0; p < 4; p++)
                a[p] = *(const ull*)&xs[kk][row * 8 + 2 * p];
            ull b[8];
            #pragma unroll
            for (int c = 0; c < 8; c++) b[c] = dup2(cs[kk][col * 8 + c]);
            #pragma unroll
            for (int p = 0; p < 4; p++)
                #pragma unroll
                for (int c = 0; c < 8; c++) fma2(acc[p][c], a[p], b[c]);
        }
    }

    float* out = g_cbn + (size_t)stage * CBSZ;
    #pragma unroll
    for (int p = 0; p < 4; p++) {
        int cg = m0 + row * 8 + 2 * p;
        #pragma unroll
        for (int c = 0; c < 8; c++) {
            int d = n0 + col * 8 + c;
            out[(size_t)cg * DIM + d]       = lo2(acc[p][c]);
            out[(size_t)(cg + 1) * DIM + d] = hi2(acc[p][c]);
        }
    }
}

// ============== mma.sync bf16 split-2 sim + fused argmax =======================
// Block: 256 thr (8 warps: 4 M x 2 N). Block tile 128 tok x 128 codes, 32 n-tiles.
// K in double-buffered 64-dim chunks (128B rows in bf16), fp32 -> bf16 hi/lo split
// on the fly. sim = Xh*Ch + Xh*Cl + Xl*Ch (fp32 accumulate, lo*lo dropped ~2^-18).
// Flattened 256-chunk stream (32 tiles x 8 chunks) with cross-tile prefetch.
#define XH_O 0
#define XL_O 16384
#define CH_O 32768
#define CL_O 49152
#define BUFSZ 65536
#define SMEM_MMA (2 * BUFSZ)      // 128KB dynamic
#define NTILES 32
#define KCHUNKS 8                 // 512 / 64 dims
#define GTOT (NTILES * KCHUNKS)   // 256

__global__ void __launch_bounds__(256, 1)
sim_mma_kernel(int stage) {
    extern __shared__ __align__(16) char smem[];
    uint32_t sb = smem_to_u32(smem);

    int tid  = threadIdx.x;
    int lane = tid & 31;
    int warp = tid >> 5;
    int wm = warp & 3;            // m offset wm*32
    int wn = warp >> 2;           // n offset wn*64

    int m0 = blockIdx.x * 128;
    const float* xn = g_xn + (size_t)m0 * DIM;
    const float* cb = g_cbn + (size_t)stage * CBSZ;

    // staging: 1024 items per 128x64 matrix (8 dims each), 4 per thread
    int srow[4], sslot[4];
    uint32_t ssw[4];
    #pragma unroll
    for (int it = 0; it < 4; it++) {
        int item = it * 256 + tid;
        srow[it]  = item >> 3;
        sslot[it] = item & 7;
        uint32_t off = (uint32_t)srow[it] * 128u + (uint32_t)sslot[it] * 16u;
        ssw[it] = SWZ(off);
    }

    // ldmatrix per-lane offsets within a 128-row x 128-byte matrix
    int a_r = wm * 32 + (lane & 15);
    int a_c = (lane >> 4) << 4;
    int b_r = wn * 64 + ((lane >> 4) << 3) + (lane & 7);
    int b_c = ((lane >> 3) & 1) << 4;

    float best[4]; int bidx[4];
    #pragma unroll
    for (int s = 0; s < 4; s++) { best[s] = -1e30f; bidx[s] = 0; }

    float acc[2][8][4];
    #pragma unroll
    for (int mf = 0; mf < 2; mf++)
        #pragma unroll
        for (int nf = 0; nf < 8; nf++)
            #pragma unroll
            for (int q = 0; q < 4; q++) acc[mf][nf][q] = 0.f;

    // prefetch chunk 0 (tile 0, k0 = 0)
    float4 xv[4][2], cv[4][2];
    #pragma unroll
    for (int it = 0; it < 4; it++) {
        const float* xp = xn + (size_t)srow[it] * DIM + sslot[it] * 8;
        const float* cp = cb + (size_t)srow[it] * DIM + sslot[it] * 8;
        xv[it][0] = *(const float4*)xp;     xv[it][1] = *(const float4*)(xp + 4);
        cv[it][0] = *(const float4*)cp;     cv[it][1] = *(const float4*)(cp + 4);
    }
    #pragma unroll
    for (int it = 0; it < 4; it++) {
        cvt_store8(smem + XH_O, smem + XL_O, ssw[it], xv[it][0], xv[it][1]);
        cvt_store8(smem + CH_O, smem + CL_O, ssw[it], cv[it][0], cv[it][1]);
    }
    __syncthreads();

    for (int gg = 0; gg < GTOT; gg++) {
        // issue global loads for chunk gg+1 (crosses tile boundaries)
        if (gg + 1 < GTOT) {
            int nt1 = (gg + 1) >> 3;
            int k1  = ((gg + 1) & 7) * 64;
            const float* cbt1 = cb + (size_t)(nt1 * 128) * DIM;
            #pragma unroll
            for (int it = 0; it < 4; it++) {
                const float* xp = xn   + (size_t)srow[it] * DIM + k1 + sslot[it] * 8;
                const float* cp = cbt1 + (size_t)srow[it] * DIM + k1 + sslot[it] * 8;
                xv[it][0] = *(const float4*)xp;  xv[it][1] = *(const float4*)(xp + 4);
                cv[it][0] = *(const float4*)cp;  cv[it][1] = *(const float4*)(cp + 4);
            }
        }
        // compute on buf[gg&1]
        uint32_t bufb = sb + (uint32_t)((gg & 1) * BUFSZ);
        #pragma unroll
        for (int ks = 0; ks < 4; ks++) {
            uint32_t ah[2][4], al[2][4];
            #pragma unroll
            for (int mf = 0; mf < 2; mf++) {
                uint32_t off = (uint32_t)(a_r + mf * 16) * 128u + (uint32_t)(ks * 32 + a_c);
                uint32_t sw = SWZ(off);
                ldm_x4(ah[mf], bufb + XH_O + sw);
                ldm_x4(al[mf], bufb + XL_O + sw);
            }
            uint32_t bh[16], bl[16];
            #pragma unroll
            for (int nf2 = 0; nf2 < 4; nf2++) {
                uint32_t off = (uint32_t)(b_r + nf2 * 16) * 128u + (uint32_t)(ks * 32 + b_c);
                uint32_t sw = SWZ(off);
                ldm_x4(&bh[nf2 * 4], bufb + CH_O + sw);
                ldm_x4(&bl[nf2 * 4], bufb + CL_O + sw);
            }
            #pragma unroll
            for (int mf = 0; mf < 2; mf++)
                #pragma unroll
                for (int nf = 0; nf < 8; nf++) {
                    mma_bf16(acc[mf][nf], ah[mf], &bh[nf * 2]);
                    mma_bf16(acc[mf][nf], ah[mf], &bl[nf * 2]);
                    mma_bf16(acc[mf][nf], al[mf], &bh[nf * 2]);
                }
        }
        // store chunk gg+1 into the other buffer
        if (gg + 1 < GTOT) {
            char* nb = smem + ((gg + 1) & 1) * BUFSZ;
            #pragma unroll
            for (int it = 0; it < 4; it++) {
                cvt_store8(nb + XH_O, nb + XL_O, ssw[it], xv[it][0], xv[it][1]);
                cvt_store8(nb + CH_O, nb + CL_O, ssw[it], cv[it][0], cv[it][1]);
            }
        }
        // tile boundary: fold acc into running argmax, reset
        if ((gg & 7) == 7) {
            int nt = gg >> 3;
            int cb0 = nt * 128 + wn * 64 + (lane & 3) * 2;
            #pragma unroll
            for (int mf = 0; mf < 2; mf++)
                #pragma unroll
                for (int nf = 0; nf < 8; nf++) {
                    int c = cb0 + nf * 8;
                    float v0 = acc[mf][nf][0], v1 = acc[mf][nf][1];
                    float v2 = acc[mf][nf][2], v3 = acc[mf][nf][3];
                    int s0 = mf * 2, s1 = mf * 2 + 1;
                    if (v0 > best[s0]) { best[s0] = v0; bidx[s0] = c; }
                    if (v1 > best[s0]) { best[s0] = v1; bidx[s0] = c + 1; }
                    if (v2 > best[s1]) { best[s1] = v2; bidx[s1] = c; }
                    if (v3 > best[s1]) { best[s1] = v3; bidx[s1] = c + 1; }
                    acc[mf][nf][0] = 0.f; acc[mf][nf][1] = 0.f;
                    acc[mf][nf][2] = 0.f; acc[mf][nf][3] = 0.f;
                }
        }
        __syncthreads();
    }

    // reduce across the 4 lanes sharing each row
    #pragma unroll
    for (int s = 0; s < 4; s++) {
        #pragma unroll
        for (int off = 1; off <= 2; off <<= 1) {
            float ov = __shfl_xor_sync(0xffffffffu, best[s], off);
            int   oi = __shfl_xor_sync(0xffffffffu, bidx[s], off);
            if (ov > best[s] || (ov == best[s] && oi < bidx[s])) {
                best[s] = ov; bidx[s] = oi;
            }
        }
    }
    __syncthreads();   // mma buffers dead; reuse smem for reduction
    float* sval = (float*)smem;              // [128][2]
    int*   sidx = (int*)(smem + 128 * 2 * 4);
    if ((lane & 3) == 0) {
        #pragma unroll
        for (int s = 0; s < 4; s++) {
            int row = wm * 32 + (s >> 1) * 16 + (lane >> 2) + (s & 1) * 8;
            sval[row * 2 + wn] = best[s];
            sidx[row * 2 + wn] = bidx[s];
        }
    }
    __syncthreads();
    if (tid < 128) {
        float v0 = sval[tid * 2], v1 = sval[tid * 2 + 1];
        int   i0 = sidx[tid * 2], i1 = sidx[tid * 2 + 1];
        int bi = (v1 > v0 || (v1 == v0 && i1 < i0)) ? i1 : i0;
        g_idx[m0 + tid] = bi;
    }
}

// ---------------- rotation-trick update per token ------------------------------
__global__ void rotate_update_kernel(int stage, float* __restrict__ out, int write_aux) {
    int warp = threadIdx.x >> 5;
    int lane = threadIdx.x & 31;
    int token = blockIdx.x * 8 + warp;

    const float4* xr = (const float4*)(g_xn + (size_t)token * DIM);
    float4*       rr = (float4*)(g_res + (size_t)token * DIM);
    int code = g_idx[token];
    const float4* qr = (const float4*)(g_cbn + (size_t)stage * CBSZ + (size_t)code * DIM);

    float4 xv[4], qv[4];
    float see = 0.f, stt = 0.f, set = 0.f;
    #pragma unroll
    for (int j = 0; j < 4; j++) {
        xv[j] = xr[lane + j * 32];
        qv[j] = qr[lane + j * 32];
        see += xv[j].x * xv[j].x + xv[j].y * xv[j].y + xv[j].z * xv[j].z + xv[j].w * xv[j].w;
        stt += qv[j].x * qv[j].x + qv[j].y * qv[j].y + qv[j].z * qv[j].z + qv[j].w * qv[j].w;
        set += xv[j].x * qv[j].x + xv[j].y * qv[j].y + xv[j].z * qv[j].z + xv[j].w * qv[j].w;
    }
    see = warp_sum(see); stt = warp_sum(stt); set = warp_sum(set);

    float ns = sqrtf(see), nt = sqrtf(stt);
    float eu = see / ns;
    float eq = set / nt;
    float nw2 = 2.f + 2.f * set / (ns * nt);
    float nw = fmaxf(sqrtf(nw2), 1e-12f);
    float cw = 2.f * (eu + eq) / (nw * nw);
    float ax = (nt / ns) * (1.f - cw / ns);
    float aq = (2.f * eu - cw) / ns;
    float scc = see - 2.f * set + stt;

    float4* qo = (float4*)(out + (size_t)token * DIM);
    float rn2 = 0.f;
    float4 rnv[4];
    #pragma unroll
    for (int j = 0; j < 4; j++) {
        float4 o;
        o.x = ax * xv[j].x + aq * qv[j].x;
        o.y = ax * xv[j].y + aq * qv[j].y;
        o.z = ax * xv[j].z + aq * qv[j].z;
        o.w = ax * xv[j].w + aq * qv[j].w;
        float4 r = rr[lane + j * 32];
        if (stage == 0) {
            qo[lane + j * 32] = o;
        } else {
            float4 prev = qo[lane + j * 32];
            prev.x += o.x; prev.y += o.y; prev.z += o.z; prev.w += o.w;
            qo[lane + j * 32] = prev;
        }
        float4 rn;
        rn.x = r.x - o.x; rn.y = r.y - o.y; rn.z = r.z - o.z; rn.w = r.w - o.w;
        rr[lane + j * 32] = rn;
        rnv[j] = rn;
        rn2 += rn.x * rn.x + rn.y * rn.y + rn.z * rn.z + rn.w * rn.w;
    }
    if (stage < NQ - 1) {
        rn2 = warp_sum(rn2);
        float inv = 1.f / fmaxf(sqrtf(rn2), 1e-12f);
        float4* xw = (float4*)(g_xn + (size_t)token * DIM);
        #pragma unroll
        for (int j = 0; j < 4; j++) {
            float4 n = make_float4(rnv[j].x * inv, rnv[j].y * inv,
                                   rnv[j].z * inv, rnv[j].w * inv);
            xw[lane + j * 32] = n;
        }
    }
    if (lane == 0 && write_aux)
        out[IDX_OFF + (size_t)token * NQ + stage] = (float)code;

    __shared__ float wscc[8];
    if (lane == 0) wscc[warp] = scc;
    __syncthreads();
    if (threadIdx.x == 0) {
        float s = 0.f;
        #pragma unroll
        for (int w = 0; w < 8; w++) s += wscc[w];
        atomicAdd(&g_loss[stage], (double)s);
    }
}

// ---------------- launch ------------------------------------------------------
extern "C" void kernel_launch(void* const* d_in, const int* in_sizes, int n_in,
                              void* d_out, int out_size) {
    const float* x         = (const float*)d_in[0];
    const float* codebooks = (const float*)d_in[1];
    const float* weights   = (const float*)d_in[2];
    float* out = (float*)d_out;
    int write_aux = (out_size >= OUT_FULL) ? 1 : 0;

    cudaFuncSetAttribute(sim_mma_kernel,
                         cudaFuncAttributeMaxDynamicSharedMemorySize, SMEM_MMA);

    zero_loss_kernel<<<1, 32>>>();
    cb_gemm_kernel<<<dim3(NC / 64, DIM / 128, NQ), 128>>>(codebooks, weights);
    cb_norm_kernel<<<NQ * NC, 128>>>();
    init_xr_kernel<<<BN, 128>>>(x);
    for (int s = 0; s < NQ; s++) {
        sim_mma_kernel<<<BN / 128, 256, SMEM_MMA>>>(s);
        rotate_update_kernel<<<BN / 8, 256>>>(s, out, write_aux);
    }
    if (write_aux) finalize_loss_kernel<<<1, 32>>>(out);
}

// round 8
// speedup vs baseline: 3.6939x; 1.2723x over previous
#include <cuda_runtime.h>
#include <cuda_bf16.h>
#include <math.h>
#include <stdint.h>

// Problem constants
#define BN     16384           // B*N tokens
#define DIM    512
#define NC     4096            // codes per stage
#define NQ     4               // stages
#define CBSZ   (NC * DIM)      // floats per stage codebook
#define QOUT_ELEMS  (BN * DIM)               // 8388608
#define IDX_OFF     QOUT_ELEMS
#define IDX_ELEMS   (BN * NQ)                // 65536
#define LOSS_OFF    (IDX_OFF + IDX_ELEMS)
#define OUT_FULL    (LOSS_OFF + NQ)

// ---------------- device scratch (static globals; no runtime alloc) ----------
__device__ float  g_cbn[(size_t)NQ * CBSZ];     // normalized implicit codebooks (32MB)
__device__ float  g_xn [(size_t)BN * DIM];      // l2norm(residual) (32MB)
__device__ float  g_res[(size_t)BN * DIM];      // residual (32MB)
__device__ __align__(16) __nv_bfloat16 g_cbh[(size_t)NQ * CBSZ];  // cb_n hi (16MB)
__device__ __align__(16) __nv_bfloat16 g_cbl[(size_t)NQ * CBSZ];  // cb_n lo (16MB)
__device__ __align__(16) __nv_bfloat16 g_xh[(size_t)BN * DIM];    // x_n hi (16MB)
__device__ __align__(16) __nv_bfloat16 g_xl[(size_t)BN * DIM];    // x_n lo (16MB)
__device__ int    g_idx[BN];
__device__ double g_loss[NQ];

// ---------------- helpers ------------------------------------------------------
__device__ __forceinline__ uint32_t smem_to_u32(const void* p) {
    uint32_t a;
    asm("{ .reg .u64 t; cvta.to.shared.u64 t, %1; cvt.u32.u64 %0, t; }" : "=r"(a) : "l"(p));
    return a;
}
__device__ __forceinline__ float warp_sum(float v) {
    #pragma unroll
    for (int o = 16; o; o >>= 1) v += __shfl_xor_sync(0xffffffffu, v, o);
    return v;
}

// ldmatrix / mma (baseline PTX ISA — valid for plain sm_103 target)
__device__ __forceinline__ void ldm_x4(uint32_t* r, uint32_t addr) {
    asm volatile("ldmatrix.sync.aligned.m8n8.x4.shared.b16 {%0,%1,%2,%3}, [%4];"
        : "=r"(r[0]), "=r"(r[1]), "=r"(r[2]), "=r"(r[3]) : "r"(addr));
}
__device__ __forceinline__ void mma_bf16(float* d, const uint32_t* a, const uint32_t* b) {
    asm volatile(
        "mma.sync.aligned.m16n8k16.row.col.f32.bf16.bf16.f32 "
        "{%0,%1,%2,%3}, {%4,%5,%6,%7}, {%8,%9}, {%0,%1,%2,%3};"
        : "+f"(d[0]), "+f"(d[1]), "+f"(d[2]), "+f"(d[3])
        : "r"(a[0]), "r"(a[1]), "r"(a[2]), "r"(a[3]), "r"(b[0]), "r"(b[1]));
}
__device__ __forceinline__ void cp16(uint32_t saddr, const void* gptr) {
    asm volatile("cp.async.cg.shared.global [%0], [%1], 16;"
        :: "r"(saddr), "l"(gptr) : "memory");
}
#define CP_COMMIT() asm volatile("cp.async.commit_group;" ::: "memory")
#define CP_WAIT0()  asm volatile("cp.async.wait_group 0;" ::: "memory")

#define SWZ(off) ((off) ^ (((off) >> 3) & 0x70u))

// bf16 split-2 packing: hi = bf16(x), lo = bf16(x - hi); pack pairs (lo half = e0)
__device__ __forceinline__ uint32_t pack_bf16(float e0, float e1) {
    uint32_t r; asm("cvt.rn.bf16x2.f32 %0, %1, %2;" : "=r"(r) : "f"(e1), "f"(e0)); return r;
}
__device__ __forceinline__ float bflo(uint32_t p) { return __uint_as_float(p << 16); }
__device__ __forceinline__ float bfhi(uint32_t p) { return __uint_as_float(p & 0xffff0000u); }

__device__ __forceinline__ void cvt_store8(char* hb, char* lb, uint32_t sw,
                                           float4 a, float4 b) {
    uint4 hv, lv;
    hv.x = pack_bf16(a.x, a.y); hv.y = pack_bf16(a.z, a.w);
    hv.z = pack_bf16(b.x, b.y); hv.w = pack_bf16(b.z, b.w);
    lv.x = pack_bf16(a.x - bflo(hv.x), a.y - bfhi(hv.x));
    lv.y = pack_bf16(a.z - bflo(hv.y), a.w - bfhi(hv.y));
    lv.z = pack_bf16(b.x - bflo(hv.z), b.y - bfhi(hv.z));
    lv.w = pack_bf16(b.z - bflo(hv.w), b.w - bfhi(hv.w));
    *(uint4*)(hb + sw) = hv;
    *(uint4*)(lb + sw) = lv;
}

// split a float4 (4 dims) into hi/lo uint2 (4 bf16 each)
__device__ __forceinline__ void split4(float4 v, uint2& h, uint2& l) {
    h.x = pack_bf16(v.x, v.y); h.y = pack_bf16(v.z, v.w);
    l.x = pack_bf16(v.x - bflo(h.x), v.y - bfhi(h.x));
    l.y = pack_bf16(v.z - bflo(h.y), v.w - bfhi(h.y));
}

// ---------------- misc small kernels -----------------------------------------
__global__ void zero_loss_kernel() {
    if (threadIdx.x < NQ) g_loss[threadIdx.x] = 0.0;
}

__global__ void finalize_loss_kernel(float* out) {
    if (threadIdx.x < NQ)
        out[LOSS_OFF + threadIdx.x] =
            (float)(g_loss[threadIdx.x] * 1.25 / (double)QOUT_ELEMS);
}

// residual = x ; x_n = x / max(||x||,1e-12) ; + bf16 hi/lo split of x_n
__global__ void init_xr_kernel(const float* __restrict__ x) {
    int row = blockIdx.x;
    int t   = threadIdx.x;
    const float4* xr = (const float4*)(x + (size_t)row * DIM);
    float4 v = xr[t];
    float s = v.x * v.x + v.y * v.y + v.z * v.z + v.w * v.w;
    s = warp_sum(s);
    __shared__ float ps[4];
    if ((t & 31) == 0) ps[t >> 5] = s;
    __syncthreads();
    float tot = ps[0] + ps[1] + ps[2] + ps[3];
    float inv = 1.0f / fmaxf(sqrtf(tot), 1e-12f);
    ((float4*)(g_res + (size_t)row * DIM))[t] = v;
    float4 n = make_float4(v.x * inv, v.y * inv, v.z * inv, v.w * inv);
    ((float4*)(g_xn + (size_t)row * DIM))[t] = n;
    uint2 h, l; split4(n, h, l);
    ((uint2*)(g_xh + (size_t)row * DIM))[t] = h;
    ((uint2*)(g_xl + (size_t)row * DIM))[t] = l;
}

// in-place row l2norm of g_cbn + bf16 hi/lo split (one block per row)
__global__ void cb_norm_kernel() {
    size_t row = blockIdx.x;
    int t = threadIdx.x;
    float4* r = (float4*)(g_cbn + row * DIM);
    float4 v = r[t];
    float s = v.x * v.x + v.y * v.y + v.z * v.z + v.w * v.w;
    s = warp_sum(s);
    __shared__ float ps[4];
    if ((t & 31) == 0) ps[t >> 5] = s;
    __syncthreads();
    float tot = ps[0] + ps[1] + ps[2] + ps[3];
    float inv = 1.0f / fmaxf(sqrtf(tot), 1e-12f);
    float4 n = make_float4(v.x * inv, v.y * inv, v.z * inv, v.w * inv);
    r[t] = n;
    uint2 h, l; split4(n, h, l);
    ((uint2*)(g_cbh + row * DIM))[t] = h;
    ((uint2*)(g_cbl + row * DIM))[t] = l;
}

// ============ implicit codebook GEMM via bf16 split-2 mma ======================
// out[s][c][d] = sum_k codebooks[s][c][k] * weights[s][d][k]  (fp32 out = g_cbn raw)
// Block 128 codes x 128 dims, 8 warps (4Mx2N), K=512 in 8 chunks of 64,
// fp32 -> bf16 hi/lo split on the fly, double-buffered smem.
#define XH_O 0
#define XL_O 16384
#define CH_O 32768
#define CL_O 49152
#define BUFSZ 65536
#define SMEM_MMA (2 * BUFSZ)      // 128KB dynamic

__global__ void __launch_bounds__(256, 1)
cb_gemm_mma_kernel(const float* __restrict__ codebooks, const float* __restrict__ weights) {
    extern __shared__ __align__(16) char smem[];
    uint32_t sb = smem_to_u32(smem);

    int tid  = threadIdx.x;
    int lane = tid & 31;
    int warp = tid >> 5;
    int wm = warp & 3;
    int wn = warp >> 2;

    int stage = blockIdx.z;
    int m0 = blockIdx.x * 128;    // codes
    int n0 = blockIdx.y * 128;    // dims
    const float* A  = codebooks + (size_t)stage * NC * DIM;
    const float* Bw = weights   + (size_t)stage * DIM * DIM;

    int srow[4], sslot[4];
    uint32_t ssw[4];
    #pragma unroll
    for (int it = 0; it < 4; it++) {
        int item = it * 256 + tid;
        srow[it]  = item >> 3;
        sslot[it] = item & 7;
        uint32_t off = (uint32_t)srow[it] * 128u + (uint32_t)sslot[it] * 16u;
        ssw[it] = SWZ(off);
    }

    int a_r = wm * 32 + (lane & 15);
    int a_c = (lane >> 4) << 4;
    int b_r = wn * 64 + ((lane >> 4) << 3) + (lane & 7);
    int b_c = ((lane >> 3) & 1) << 4;

    float acc[2][8][4];
    #pragma unroll
    for (int mf = 0; mf < 2; mf++)
        #pragma unroll
        for (int nf = 0; nf < 8; nf++)
            #pragma unroll
            for (int q = 0; q < 4; q++) acc[mf][nf][q] = 0.f;

    float4 xv[4][2], cv[4][2];
    #pragma unroll
    for (int it = 0; it < 4; it++) {
        const float* xp = A  + (size_t)(m0 + srow[it]) * DIM + sslot[it] * 8;
        const float* cp = Bw + (size_t)(n0 + srow[it]) * DIM + sslot[it] * 8;
        xv[it][0] = *(const float4*)xp;  xv[it][1] = *(const float4*)(xp + 4);
        cv[it][0] = *(const float4*)cp;  cv[it][1] = *(const float4*)(cp + 4);
    }
    #pragma unroll
    for (int it = 0; it < 4; it++) {
        cvt_store8(smem + XH_O, smem + XL_O, ssw[it], xv[it][0], xv[it][1]);
        cvt_store8(smem + CH_O, smem + CL_O, ssw[it], cv[it][0], cv[it][1]);
    }
    __syncthreads();

    for (int g = 0; g < 8; g++) {
        if (g + 1 < 8) {
            int k1 = (g + 1) * 64;
            #pragma unroll
            for (int it = 0; it < 4; it++) {
                const float* xp = A  + (size_t)(m0 + srow[it]) * DIM + k1 + sslot[it] * 8;
                const float* cp = Bw + (size_t)(n0 + srow[it]) * DIM + k1 + sslot[it] * 8;
                xv[it][0] = *(const float4*)xp;  xv[it][1] = *(const float4*)(xp + 4);
                cv[it][0] = *(const float4*)cp;  cv[it][1] = *(const float4*)(cp + 4);
            }
        }
        uint32_t bufb = sb + (uint32_t)((g & 1) * BUFSZ);
        #pragma unroll
        for (int ks = 0; ks < 4; ks++) {
            uint32_t ah[2][4], al[2][4];
            #pragma unroll
            for (int mf = 0; mf < 2; mf++) {
                uint32_t off = (uint32_t)(a_r + mf * 16) * 128u + (uint32_t)(ks * 32 + a_c);
                uint32_t sw = SWZ(off);
                ldm_x4(ah[mf], bufb + XH_O + sw);
                ldm_x4(al[mf], bufb + XL_O + sw);
            }
            uint32_t bh[16], bl[16];
            #pragma unroll
            for (int nf2 = 0; nf2 < 4; nf2++) {
                uint32_t off = (uint32_t)(b_r + nf2 * 16) * 128u + (uint32_t)(ks * 32 + b_c);
                uint32_t sw = SWZ(off);
                ldm_x4(&bh[nf2 * 4], bufb + CH_O + sw);
                ldm_x4(&bl[nf2 * 4], bufb + CL_O + sw);
            }
            #pragma unroll
            for (int mf = 0; mf < 2; mf++)
                #pragma unroll
                for (int nf = 0; nf < 8; nf++) {
                    mma_bf16(acc[mf][nf], ah[mf], &bh[nf * 2]);
                    mma_bf16(acc[mf][nf], ah[mf], &bl[nf * 2]);
                    mma_bf16(acc[mf][nf], al[mf], &bh[nf * 2]);
                }
        }
        if (g + 1 < 8) {
            char* nb = smem + ((g + 1) & 1) * BUFSZ;
            #pragma unroll
            for (int it = 0; it < 4; it++) {
                cvt_store8(nb + XH_O, nb + XL_O, ssw[it], xv[it][0], xv[it][1]);
                cvt_store8(nb + CH_O, nb + CL_O, ssw[it], cv[it][0], cv[it][1]);
            }
        }
        __syncthreads();
    }

    // store fp32 result (raw implicit codebook, pre-norm)
    float* out = g_cbn + (size_t)stage * CBSZ;
    int r0 = lane >> 2, c0 = (lane & 3) * 2;
    #pragma unroll
    for (int mf = 0; mf < 2; mf++) {
        int row = m0 + wm * 32 + mf * 16 + r0;
        #pragma unroll
        for (int nf = 0; nf < 8; nf++) {
            int col = n0 + wn * 64 + nf * 8 + c0;
            out[(size_t)row * DIM + col]           = acc[mf][nf][0];
            out[(size_t)row * DIM + col + 1]       = acc[mf][nf][1];
            out[(size_t)(row + 8) * DIM + col]     = acc[mf][nf][2];
            out[(size_t)(row + 8) * DIM + col + 1] = acc[mf][nf][3];
        }
    }
}

// ============ sim + fused argmax: pre-split bf16 inputs, cp.async staging ======
// Block 128 tokens x (32 n-tiles of 128 codes), 8 warps (4Mx2N).
// K in double-buffered 64-dim chunks; staging is a raw cp.async copy of the
// pre-split hi/lo bf16 arrays. sim = Xh*Ch + Xh*Cl + Xl*Ch (fp32 accumulate).
#define NTILES 32
#define KCHUNKS 8                 // 512 / 64 dims
#define GTOT (NTILES * KCHUNKS)   // 256

__global__ void __launch_bounds__(256, 1)
sim_mma_kernel(int stage) {
    extern __shared__ __align__(16) char smem[];
    uint32_t sb = smem_to_u32(smem);

    int tid  = threadIdx.x;
    int lane = tid & 31;
    int warp = tid >> 5;
    int wm = warp & 3;
    int wn = warp >> 2;

    int m0 = blockIdx.x * 128;
    const char* xhp = (const char*)(g_xh + (size_t)m0 * DIM);
    const char* xlp = (const char*)(g_xl + (size_t)m0 * DIM);
    const char* chp = (const char*)(g_cbh + (size_t)stage * CBSZ);
    const char* clp = (const char*)(g_cbl + (size_t)stage * CBSZ);

    int srow[4], sslot[4];
    uint32_t ssw[4];
    size_t roff[4];                      // byte offset within a row-major bf16 block
    #pragma unroll
    for (int it = 0; it < 4; it++) {
        int item = it * 256 + tid;
        srow[it]  = item >> 3;
        sslot[it] = item & 7;
        uint32_t off = (uint32_t)srow[it] * 128u + (uint32_t)sslot[it] * 16u;
        ssw[it] = SWZ(off);
        roff[it] = (size_t)srow[it] * (DIM * 2) + (size_t)sslot[it] * 16;
    }

    int a_r = wm * 32 + (lane & 15);
    int a_c = (lane >> 4) << 4;
    int b_r = wn * 64 + ((lane >> 4) << 3) + (lane & 7);
    int b_c = ((lane >> 3) & 1) << 4;

    float best[4]; int bidx[4];
    #pragma unroll
    for (int s = 0; s < 4; s++) { best[s] = -1e30f; bidx[s] = 0; }

    float acc[2][8][4];
    #pragma unroll
    for (int mf = 0; mf < 2; mf++)
        #pragma unroll
        for (int nf = 0; nf < 8; nf++)
            #pragma unroll
            for (int q = 0; q < 4; q++) acc[mf][nf][q] = 0.f;

    // prologue: async-copy chunk 0 (tile 0, k0=0) into buf 0
    {
        uint32_t nb = sb;
        #pragma unroll
        for (int it = 0; it < 4; it++) {
            cp16(nb + XH_O + ssw[it], xhp + roff[it]);
            cp16(nb + XL_O + ssw[it], xlp + roff[it]);
            cp16(nb + CH_O + ssw[it], chp + roff[it]);
            cp16(nb + CL_O + ssw[it], clp + roff[it]);
        }
        CP_COMMIT();
        CP_WAIT0();
        __syncthreads();
    }

    for (int gg = 0; gg < GTOT; gg++) {
        // async-copy chunk gg+1 (crosses tile boundaries) into the other buffer
        if (gg + 1 < GTOT) {
            int nt1 = (gg + 1) >> 3;
            size_t kb1 = (size_t)(((gg + 1) & 7) * 64) * 2;         // byte offset of k0
            size_t cb1 = (size_t)(nt1 * 128) * (DIM * 2) + kb1;     // C block byte base
            uint32_t nb = sb + (uint32_t)(((gg + 1) & 1) * BUFSZ);
            #pragma unroll
            for (int it = 0; it < 4; it++) {
                cp16(nb + XH_O + ssw[it], xhp + kb1 + roff[it]);
                cp16(nb + XL_O + ssw[it], xlp + kb1 + roff[it]);
                cp16(nb + CH_O + ssw[it], chp + cb1 + roff[it]);
                cp16(nb + CL_O + ssw[it], clp + cb1 + roff[it]);
            }
            CP_COMMIT();
        }
        // compute on buf[gg&1]
        uint32_t bufb = sb + (uint32_t)((gg & 1) * BUFSZ);
        #pragma unroll
        for (int ks = 0; ks < 4; ks++) {
            uint32_t ah[2][4], al[2][4];
            #pragma unroll
            for (int mf = 0; mf < 2; mf++) {
                uint32_t off = (uint32_t)(a_r + mf * 16) * 128u + (uint32_t)(ks * 32 + a_c);
                uint32_t sw = SWZ(off);
                ldm_x4(ah[mf], bufb + XH_O + sw);
                ldm_x4(al[mf], bufb + XL_O + sw);
            }
            uint32_t bh[16], bl[16];
            #pragma unroll
            for (int nf2 = 0; nf2 < 4; nf2++) {
                uint32_t off = (uint32_t)(b_r + nf2 * 16) * 128u + (uint32_t)(ks * 32 + b_c);
                uint32_t sw = SWZ(off);
                ldm_x4(&bh[nf2 * 4], bufb + CH_O + sw);
                ldm_x4(&bl[nf2 * 4], bufb + CL_O + sw);
            }
            #pragma unroll
            for (int mf = 0; mf < 2; mf++)
                #pragma unroll
                for (int nf = 0; nf < 8; nf++) {
                    mma_bf16(acc[mf][nf], ah[mf], &bh[nf * 2]);
                    mma_bf16(acc[mf][nf], ah[mf], &bl[nf * 2]);
                    mma_bf16(acc[mf][nf], al[mf], &bh[nf * 2]);
                }
        }
        // tile boundary: fold acc into running argmax, reset
        if ((gg & 7) == 7) {
            int nt = gg >> 3;
            int cb0 = nt * 128 + wn * 64 + (lane & 3) * 2;
            #pragma unroll
            for (int mf = 0; mf < 2; mf++)
                #pragma unroll
                for (int nf = 0; nf < 8; nf++) {
                    int c = cb0 + nf * 8;
                    float v0 = acc[mf][nf][0], v1 = acc[mf][nf][1];
                    float v2 = acc[mf][nf][2], v3 = acc[mf][nf][3];
                    int s0 = mf * 2, s1 = mf * 2 + 1;
                    if (v0 > best[s0]) { best[s0] = v0; bidx[s0] = c; }
                    if (v1 > best[s0]) { best[s0] = v1; bidx[s0] = c + 1; }
                    if (v2 > best[s1]) { best[s1] = v2; bidx[s1] = c; }
                    if (v3 > best[s1]) { best[s1] = v3; bidx[s1] = c + 1; }
                    acc[mf][nf][0] = 0.f; acc[mf][nf][1] = 0.f;
                    acc[mf][nf][2] = 0.f; acc[mf][nf][3] = 0.f;
                }
        }
        if (gg + 1 < GTOT) CP_WAIT0();
        __syncthreads();
    }

    // reduce across the 4 lanes sharing each row
    #pragma unroll
    for (int s = 0; s < 4; s++) {
        #pragma unroll
        for (int off = 1; off <= 2; off <<= 1) {
            float ov = __shfl_xor_sync(0xffffffffu, best[s], off);
            int   oi = __shfl_xor_sync(0xffffffffu, bidx[s], off);
            if (ov > best[s] || (ov == best[s] && oi < bidx[s])) {
                best[s] = ov; bidx[s] = oi;
            }
        }
    }
    __syncthreads();   // mma buffers dead; reuse smem for reduction
    float* sval = (float*)smem;              // [128][2]
    int*   sidx = (int*)(smem + 128 * 2 * 4);
    if ((lane & 3) == 0) {
        #pragma unroll
        for (int s = 0; s < 4; s++) {
            int row = wm * 32 + (s >> 1) * 16 + (lane >> 2) + (s & 1) * 8;
            sval[row * 2 + wn] = best[s];
            sidx[row * 2 + wn] = bidx[s];
        }
    }
    __syncthreads();
    if (tid < 128) {
        float v0 = sval[tid * 2], v1 = sval[tid * 2 + 1];
        int   i0 = sidx[tid * 2], i1 = sidx[tid * 2 + 1];
        int bi = (v1 > v0 || (v1 == v0 && i1 < i0)) ? i1 : i0;
        g_idx[m0 + tid] = bi;
    }
}

// ---------------- rotation-trick update per token ------------------------------
__global__ void rotate_update_kernel(int stage, float* __restrict__ out, int write_aux) {
    int warp = threadIdx.x >> 5;
    int lane = threadIdx.x & 31;
    int token = blockIdx.x * 8 + warp;

    const float4* xr = (const float4*)(g_xn + (size_t)token * DIM);
    float4*       rr = (float4*)(g_res + (size_t)token * DIM);
    int code = g_idx[token];
    const float4* qr = (const float4*)(g_cbn + (size_t)stage * CBSZ + (size_t)code * DIM);

    float4 xv[4], qv[4];
    float see = 0.f, stt = 0.f, set = 0.f;
    #pragma unroll
    for (int j = 0; j < 4; j++) {
        xv[j] = xr[lane + j * 32];
        qv[j] = qr[lane + j * 32];
        see += xv[j].x * xv[j].x + xv[j].y * xv[j].y + xv[j].z * xv[j].z + xv[j].w * xv[j].w;
        stt += qv[j].x * qv[j].x + qv[j].y * qv[j].y + qv[j].z * qv[j].z + qv[j].w * qv[j].w;
        set += xv[j].x * qv[j].x + xv[j].y * qv[j].y + xv[j].z * qv[j].z + xv[j].w * qv[j].w;
    }
    see = warp_sum(see); stt = warp_sum(stt); set = warp_sum(set);

    float ns = sqrtf(see), nt = sqrtf(stt);
    float eu = see / ns;
    float eq = set / nt;
    float nw2 = 2.f + 2.f * set / (ns * nt);
    float nw = fmaxf(sqrtf(nw2), 1e-12f);
    float cw = 2.f * (eu + eq) / (nw * nw);
    float ax = (nt / ns) * (1.f - cw / ns);
    float aq = (2.f * eu - cw) / ns;
    float scc = see - 2.f * set + stt;

    float4* qo = (float4*)(out + (size_t)token * DIM);
    float rn2 = 0.f;
    float4 rnv[4];
    #pragma unroll
    for (int j = 0; j < 4; j++) {
        float4 o;
        o.x = ax * xv[j].x + aq * qv[j].x;
        o.y = ax * xv[j].y + aq * qv[j].y;
        o.z = ax * xv[j].z + aq * qv[j].z;
        o.w = ax * xv[j].w + aq * qv[j].w;
        float4 r = rr[lane + j * 32];
        if (stage == 0) {
            qo[lane + j * 32] = o;
        } else {
            float4 prev = qo[lane + j * 32];
            prev.x += o.x; prev.y += o.y; prev.z += o.z; prev.w += o.w;
            qo[lane + j * 32] = prev;
        }
        float4 rn;
        rn.x = r.x - o.x; rn.y = r.y - o.y; rn.z = r.z - o.z; rn.w = r.w - o.w;
        rr[lane + j * 32] = rn;
        rnv[j] = rn;
        rn2 += rn.x * rn.x + rn.y * rn.y + rn.z * rn.z + rn.w * rn.w;
    }
    if (stage < NQ - 1) {
        rn2 = warp_sum(rn2);
        float inv = 1.f / fmaxf(sqrtf(rn2), 1e-12f);
        float4* xw  = (float4*)(g_xn + (size_t)token * DIM);
        uint2*  xhw = (uint2*)(g_xh + (size_t)token * DIM);
        uint2*  xlw = (uint2*)(g_xl + (size_t)token * DIM);
        #pragma unroll
        for (int j = 0; j < 4; j++) {
            float4 n = make_float4(rnv[j].x * inv, rnv[j].y * inv,
                                   rnv[j].z * inv, rnv[j].w * inv);
            xw[lane + j * 32] = n;
            uint2 h, l; split4(n, h, l);
            xhw[lane + j * 32] = h;
            xlw[lane + j * 32] = l;
        }
    }
    if (lane == 0 && write_aux)
        out[IDX_OFF + (size_t)token * NQ + stage] = (float)code;

    __shared__ float wscc[8];
    if (lane == 0) wscc[warp] = scc;
    __syncthreads();
    if (threadIdx.x == 0) {
        float s = 0.f;
        #pragma unroll
        for (int w = 0; w < 8; w++) s += wscc[w];
        atomicAdd(&g_loss[stage], (double)s);
    }
}

// ---------------- launch ------------------------------------------------------
extern "C" void kernel_launch(void* const* d_in, const int* in_sizes, int n_in,
                              void* d_out, int out_size) {
    const float* x         = (const float*)d_in[0];
    const float* codebooks = (const float*)d_in[1];
    const float* weights   = (const float*)d_in[2];
    float* out = (float*)d_out;
    int write_aux = (out_size >= OUT_FULL) ? 1 : 0;

    cudaFuncSetAttribute(sim_mma_kernel,
                         cudaFuncAttributeMaxDynamicSharedMemorySize, SMEM_MMA);
    cudaFuncSetAttribute(cb_gemm_mma_kernel,
                         cudaFuncAttributeMaxDynamicSharedMemorySize, SMEM_MMA);

    zero_loss_kernel<<<1, 32>>>();
    cb_gemm_mma_kernel<<<dim3(NC / 128, DIM / 128, NQ), 256, SMEM_MMA>>>(codebooks, weights);
    cb_norm_kernel<<<NQ * NC, 128>>>();
    init_xr_kernel<<<BN, 128>>>(x);
    for (int s = 0; s < NQ; s++) {
        sim_mma_kernel<<<BN / 128, 256, SMEM_MMA>>>(s);
        rotate_update_kernel<<<BN / 8, 256>>>(s, out, write_aux);
    }
    if (write_aux) finalize_loss_kernel<<<1, 32>>>(out);
}

// round 9
// speedup vs baseline: 4.1626x; 1.1269x over previous
#include <cuda_runtime.h>
#include <cuda_bf16.h>
#include <math.h>
#include <stdint.h>

// Problem constants
#define BN     16384           // B*N tokens
#define DIM    512
#define NC     4096            // codes per stage
#define NQ     4               // stages
#define CBSZ   (NC * DIM)      // floats per stage codebook
#define QOUT_ELEMS  (BN * DIM)               // 8388608
#define IDX_OFF     QOUT_ELEMS
#define IDX_ELEMS   (BN * NQ)                // 65536
#define LOSS_OFF    (IDX_OFF + IDX_ELEMS)
#define OUT_FULL    (LOSS_OFF + NQ)

// ---------------- device scratch (static globals; no runtime alloc) ----------
__device__ float  g_cbn[(size_t)NQ * CBSZ];     // normalized implicit codebooks (32MB)
__device__ float  g_res[(size_t)BN * DIM];      // residual (32MB)
__device__ float  g_innorm[BN];                 // 1/||residual|| per token
__device__ __align__(16) __nv_bfloat16 g_cbh[(size_t)NQ * CBSZ];  // cb_n hi (16MB)
__device__ __align__(16) __nv_bfloat16 g_cbl[(size_t)NQ * CBSZ];  // cb_n lo (16MB)
__device__ __align__(16) __nv_bfloat16 g_xh[(size_t)BN * DIM];    // x_n hi (16MB)
__device__ __align__(16) __nv_bfloat16 g_xl[(size_t)BN * DIM];    // x_n lo (16MB)
__device__ unsigned long long g_best[BN];       // packed (keyed sim, ~idx)
__device__ double g_loss[NQ];

// ---------------- helpers ------------------------------------------------------
__device__ __forceinline__ uint32_t smem_to_u32(const void* p) {
    uint32_t a;
    asm("{ .reg .u64 t; cvta.to.shared.u64 t, %1; cvt.u32.u64 %0, t; }" : "=r"(a) : "l"(p));
    return a;
}
__device__ __forceinline__ float warp_sum(float v) {
    #pragma unroll
    for (int o = 16; o; o >>= 1) v += __shfl_xor_sync(0xffffffffu, v, o);
    return v;
}

// order-preserving float->uint key; pack with ~idx so atomicMax picks
// (max value, then smallest index) — exactly jnp.argmax first-max semantics.
__device__ __forceinline__ unsigned long long pack_key(float v, int idx) {
    unsigned u = __float_as_uint(v);
    u = (u & 0x80000000u) ? ~u : (u | 0x80000000u);
    return ((unsigned long long)u << 32)
         | (unsigned long long)(0xFFFFFFFFu - (unsigned)idx);
}

// ldmatrix / mma (baseline PTX ISA — valid for plain sm_103 target)
__device__ __forceinline__ void ldm_x4(uint32_t* r, uint32_t addr) {
    asm volatile("ldmatrix.sync.aligned.m8n8.x4.shared.b16 {%0,%1,%2,%3}, [%4];"
        : "=r"(r[0]), "=r"(r[1]), "=r"(r[2]), "=r"(r[3]) : "r"(addr));
}
__device__ __forceinline__ void mma_bf16(float* d, const uint32_t* a, const uint32_t* b) {
    asm volatile(
        "mma.sync.aligned.m16n8k16.row.col.f32.bf16.bf16.f32 "
        "{%0,%1,%2,%3}, {%4,%5,%6,%7}, {%8,%9}, {%0,%1,%2,%3};"
        : "+f"(d[0]), "+f"(d[1]), "+f"(d[2]), "+f"(d[3])
        : "r"(a[0]), "r"(a[1]), "r"(a[2]), "r"(a[3]), "r"(b[0]), "r"(b[1]));
}
__device__ __forceinline__ void cp16(uint32_t saddr, const void* gptr) {
    asm volatile("cp.async.cg.shared.global [%0], [%1], 16;"
        :: "r"(saddr), "l"(gptr) : "memory");
}
#define CP_COMMIT() asm volatile("cp.async.commit_group;" ::: "memory")
#define CP_WAIT0()  asm volatile("cp.async.wait_group 0;" ::: "memory")

#define SWZ(off) ((off) ^ (((off) >> 3) & 0x70u))

// bf16 split-2 packing: hi = bf16(x), lo = bf16(x - hi); pack pairs (lo half = e0)
__device__ __forceinline__ uint32_t pack_bf16(float e0, float e1) {
    uint32_t r; asm("cvt.rn.bf16x2.f32 %0, %1, %2;" : "=r"(r) : "f"(e1), "f"(e0)); return r;
}
__device__ __forceinline__ float bflo(uint32_t p) { return __uint_as_float(p << 16); }
__device__ __forceinline__ float bfhi(uint32_t p) { return __uint_as_float(p & 0xffff0000u); }

__device__ __forceinline__ void cvt_store8(char* hb, char* lb, uint32_t sw,
                                           float4 a, float4 b) {
    uint4 hv, lv;
    hv.x = pack_bf16(a.x, a.y); hv.y = pack_bf16(a.z, a.w);
    hv.z = pack_bf16(b.x, b.y); hv.w = pack_bf16(b.z, b.w);
    lv.x = pack_bf16(a.x - bflo(hv.x), a.y - bfhi(hv.x));
    lv.y = pack_bf16(a.z - bflo(hv.y), a.w - bfhi(hv.y));
    lv.z = pack_bf16(b.x - bflo(hv.z), b.y - bfhi(hv.z));
    lv.w = pack_bf16(b.z - bflo(hv.w), b.w - bfhi(hv.w));
    *(uint4*)(hb + sw) = hv;
    *(uint4*)(lb + sw) = lv;
}

__device__ __forceinline__ void split4(float4 v, uint2& h, uint2& l) {
    h.x = pack_bf16(v.x, v.y); h.y = pack_bf16(v.z, v.w);
    l.x = pack_bf16(v.x - bflo(h.x), v.y - bfhi(h.x));
    l.y = pack_bf16(v.z - bflo(h.y), v.w - bfhi(h.y));
}

// ---------------- misc small kernels -----------------------------------------
__global__ void zero_loss_kernel() {
    if (threadIdx.x < NQ) g_loss[threadIdx.x] = 0.0;
}
__global__ void clear_best_kernel() {
    g_best[blockIdx.x * 1024 + threadIdx.x] = 0ull;
}
__global__ void finalize_loss_kernel(float* out) {
    if (threadIdx.x < NQ)
        out[LOSS_OFF + threadIdx.x] =
            (float)(g_loss[threadIdx.x] * 1.25 / (double)QOUT_ELEMS);
}

// residual = x ; inv = 1/max(||x||,1e-12) ; bf16 hi/lo split of x*inv
__global__ void init_xr_kernel(const float* __restrict__ x) {
    int row = blockIdx.x;
    int t   = threadIdx.x;
    const float4* xr = (const float4*)(x + (size_t)row * DIM);
    float4 v = xr[t];
    float s = v.x * v.x + v.y * v.y + v.z * v.z + v.w * v.w;
    s = warp_sum(s);
    __shared__ float ps[4];
    if ((t & 31) == 0) ps[t >> 5] = s;
    __syncthreads();
    float tot = ps[0] + ps[1] + ps[2] + ps[3];
    float inv = 1.0f / fmaxf(sqrtf(tot), 1e-12f);
    ((float4*)(g_res + (size_t)row * DIM))[t] = v;
    if (t == 0) g_innorm[row] = inv;
    float4 n = make_float4(v.x * inv, v.y * inv, v.z * inv, v.w * inv);
    uint2 h, l; split4(n, h, l);
    ((uint2*)(g_xh + (size_t)row * DIM))[t] = h;
    ((uint2*)(g_xl + (size_t)row * DIM))[t] = l;
}

// in-place row l2norm of g_cbn + bf16 hi/lo split (one block per row)
__global__ void cb_norm_kernel() {
    size_t row = blockIdx.x;
    int t = threadIdx.x;
    float4* r = (float4*)(g_cbn + row * DIM);
    float4 v = r[t];
    float s = v.x * v.x + v.y * v.y + v.z * v.z + v.w * v.w;
    s = warp_sum(s);
    __shared__ float ps[4];
    if ((t & 31) == 0) ps[t >> 5] = s;
    __syncthreads();
    float tot = ps[0] + ps[1] + ps[2] + ps[3];
    float inv = 1.0f / fmaxf(sqrtf(tot), 1e-12f);
    float4 n = make_float4(v.x * inv, v.y * inv, v.z * inv, v.w * inv);
    r[t] = n;
    uint2 h, l; split4(n, h, l);
    ((uint2*)(g_cbh + row * DIM))[t] = h;
    ((uint2*)(g_cbl + row * DIM))[t] = l;
}

// ============ implicit codebook GEMM via bf16 split-2 mma ======================
#define XH_O 0
#define XL_O 16384
#define CH_O 32768
#define CL_O 49152
#define BUFSZ 65536
#define SMEM_MMA (2 * BUFSZ)      // 128KB dynamic

__global__ void __launch_bounds__(256, 1)
cb_gemm_mma_kernel(const float* __restrict__ codebooks, const float* __restrict__ weights) {
    extern __shared__ __align__(16) char smem[];
    uint32_t sb = smem_to_u32(smem);

    int tid  = threadIdx.x;
    int lane = tid & 31;
    int warp = tid >> 5;
    int wm = warp & 3;
    int wn = warp >> 2;

    int stage = blockIdx.z;
    int m0 = blockIdx.x * 128;    // codes
    int n0 = blockIdx.y * 128;    // dims
    const float* A  = codebooks + (size_t)stage * NC * DIM;
    const float* Bw = weights   + (size_t)stage * DIM * DIM;

    int srow[4], sslot[4];
    uint32_t ssw[4];
    #pragma unroll
    for (int it = 0; it < 4; it++) {
        int item = it * 256 + tid;
        srow[it]  = item >> 3;
        sslot[it] = item & 7;
        uint32_t off = (uint32_t)srow[it] * 128u + (uint32_t)sslot[it] * 16u;
        ssw[it] = SWZ(off);
    }

    int a_r = wm * 32 + (lane & 15);
    int a_c = (lane >> 4) << 4;
    int b_r = wn * 64 + ((lane >> 4) << 3) + (lane & 7);
    int b_c = ((lane >> 3) & 1) << 4;

    float acc[2][8][4];
    #pragma unroll
    for (int mf = 0; mf < 2; mf++)
        #pragma unroll
        for (int nf = 0; nf < 8; nf++)
            #pragma unroll
            for (int q = 0; q < 4; q++) acc[mf][nf][q] = 0.f;

    float4 xv[4][2], cv[4][2];
    #pragma unroll
    for (int it = 0; it < 4; it++) {
        const float* xp = A  + (size_t)(m0 + srow[it]) * DIM + sslot[it] * 8;
        const float* cp = Bw + (size_t)(n0 + srow[it]) * DIM + sslot[it] * 8;
        xv[it][0] = *(const float4*)xp;  xv[it][1] = *(const float4*)(xp + 4);
        cv[it][0] = *(const float4*)cp;  cv[it][1] = *(const float4*)(cp + 4);
    }
    #pragma unroll
    for (int it = 0; it < 4; it++) {
        cvt_store8(smem + XH_O, smem + XL_O, ssw[it], xv[it][0], xv[it][1]);
        cvt_store8(smem + CH_O, smem + CL_O, ssw[it], cv[it][0], cv[it][1]);
    }
    __syncthreads();

    for (int g = 0; g < 8; g++) {
        if (g + 1 < 8) {
            int k1 = (g + 1) * 64;
            #pragma unroll
            for (int it = 0; it < 4; it++) {
                const float* xp = A  + (size_t)(m0 + srow[it]) * DIM + k1 + sslot[it] * 8;
                const float* cp = Bw + (size_t)(n0 + srow[it]) * DIM + k1 + sslot[it] * 8;
                xv[it][0] = *(const float4*)xp;  xv[it][1] = *(const float4*)(xp + 4);
                cv[it][0] = *(const float4*)cp;  cv[it][1] = *(const float4*)(cp + 4);
            }
        }
        uint32_t bufb = sb + (uint32_t)((g & 1) * BUFSZ);
        #pragma unroll
        for (int ks = 0; ks < 4; ks++) {
            uint32_t ah[2][4], al[2][4];
            #pragma unroll
            for (int mf = 0; mf < 2; mf++) {
                uint32_t off = (uint32_t)(a_r + mf * 16) * 128u + (uint32_t)(ks * 32 + a_c);
                uint32_t sw = SWZ(off);
                ldm_x4(ah[mf], bufb + XH_O + sw);
                ldm_x4(al[mf], bufb + XL_O + sw);
            }
            uint32_t bh[16], bl[16];
            #pragma unroll
            for (int nf2 = 0; nf2 < 4; nf2++) {
                uint32_t off = (uint32_t)(b_r + nf2 * 16) * 128u + (uint32_t)(ks * 32 + b_c);
                uint32_t sw = SWZ(off);
                ldm_x4(&bh[nf2 * 4], bufb + CH_O + sw);
                ldm_x4(&bl[nf2 * 4], bufb + CL_O + sw);
            }
            #pragma unroll
            for (int mf = 0; mf < 2; mf++)
                #pragma unroll
                for (int nf = 0; nf < 8; nf++) {
                    mma_bf16(acc[mf][nf], ah[mf], &bh[nf * 2]);
                    mma_bf16(acc[mf][nf], ah[mf], &bl[nf * 2]);
                    mma_bf16(acc[mf][nf], al[mf], &bh[nf * 2]);
                }
        }
        if (g + 1 < 8) {
            char* nb = smem + ((g + 1) & 1) * BUFSZ;
            #pragma unroll
            for (int it = 0; it < 4; it++) {
                cvt_store8(nb + XH_O, nb + XL_O, ssw[it], xv[it][0], xv[it][1]);
                cvt_store8(nb + CH_O, nb + CL_O, ssw[it], cv[it][0], cv[it][1]);
            }
        }
        __syncthreads();
    }

    float* out = g_cbn + (size_t)stage * CBSZ;
    int r0 = lane >> 2, c0 = (lane & 3) * 2;
    #pragma unroll
    for (int mf = 0; mf < 2; mf++) {
        int row = m0 + wm * 32 + mf * 16 + r0;
        #pragma unroll
        for (int nf = 0; nf < 8; nf++) {
            int col = n0 + wn * 64 + nf * 8 + c0;
            out[(size_t)row * DIM + col]           = acc[mf][nf][0];
            out[(size_t)row * DIM + col + 1]       = acc[mf][nf][1];
            out[(size_t)(row + 8) * DIM + col]     = acc[mf][nf][2];
            out[(size_t)(row + 8) * DIM + col + 1] = acc[mf][nf][3];
        }
    }
}

// ============ sim + fused argmax: 1024 CTAs, packed-atomicMax merge ============
// CTA = (token-tile of 128) x (code-eighth of 512). 4 n-tiles of 128 codes each,
// K in double-buffered 64-dim chunks; staging = cp.async of pre-split bf16 hi/lo.
// sim = Xh*Ch + Xh*Cl + Xl*Ch (fp32 accumulate).
#define NTILES 4
#define KCHUNKS 8                 // 512 / 64 dims
#define GTOT (NTILES * KCHUNKS)   // 32

__global__ void __launch_bounds__(256, 1)
sim_mma_kernel(int stage) {
    extern __shared__ __align__(16) char smem[];
    uint32_t sb = smem_to_u32(smem);

    int tid  = threadIdx.x;
    int lane = tid & 31;
    int warp = tid >> 5;
    int wm = warp & 3;
    int wn = warp >> 2;

    int tilei  = blockIdx.x >> 3;
    int eighth = blockIdx.x & 7;
    int m0 = tilei * 128;
    int eb = eighth * 512;        // code base of this CTA's range

    const char* xhp = (const char*)(g_xh + (size_t)m0 * DIM);
    const char* xlp = (const char*)(g_xl + (size_t)m0 * DIM);
    const char* chp = (const char*)(g_cbh + (size_t)stage * CBSZ + (size_t)eb * DIM);
    const char* clp = (const char*)(g_cbl + (size_t)stage * CBSZ + (size_t)eb * DIM);

    int srow[4], sslot[4];
    uint32_t ssw[4];
    size_t roff[4];
    #pragma unroll
    for (int it = 0; it < 4; it++) {
        int item = it * 256 + tid;
        srow[it]  = item >> 3;
        sslot[it] = item & 7;
        uint32_t off = (uint32_t)srow[it] * 128u + (uint32_t)sslot[it] * 16u;
        ssw[it] = SWZ(off);
        roff[it] = (size_t)srow[it] * (DIM * 2) + (size_t)sslot[it] * 16;
    }

    int a_r = wm * 32 + (lane & 15);
    int a_c = (lane >> 4) << 4;
    int b_r = wn * 64 + ((lane >> 4) << 3) + (lane & 7);
    int b_c = ((lane >> 3) & 1) << 4;

    float best[4]; int bidx[4];
    #pragma unroll
    for (int s = 0; s < 4; s++) { best[s] = -1e30f; bidx[s] = 0; }

    float acc[2][8][4];
    #pragma unroll
    for (int mf = 0; mf < 2; mf++)
        #pragma unroll
        for (int nf = 0; nf < 8; nf++)
            #pragma unroll
            for (int q = 0; q < 4; q++) acc[mf][nf][q] = 0.f;

    // prologue: async-copy chunk 0 into buf 0
    {
        uint32_t nb = sb;
        #pragma unroll
        for (int it = 0; it < 4; it++) {
            cp16(nb + XH_O + ssw[it], xhp + roff[it]);
            cp16(nb + XL_O + ssw[it], xlp + roff[it]);
            cp16(nb + CH_O + ssw[it], chp + roff[it]);
            cp16(nb + CL_O + ssw[it], clp + roff[it]);
        }
        CP_COMMIT();
        CP_WAIT0();
        __syncthreads();
    }

    for (int gg = 0; gg < GTOT; gg++) {
        if (gg + 1 < GTOT) {
            int nt1 = (gg + 1) >> 3;
            size_t kb1 = (size_t)(((gg + 1) & 7) * 64) * 2;
            size_t cb1 = (size_t)(nt1 * 128) * (DIM * 2) + kb1;
            uint32_t nb = sb + (uint32_t)(((gg + 1) & 1) * BUFSZ);
            #pragma unroll
            for (int it = 0; it < 4; it++) {
                cp16(nb + XH_O + ssw[it], xhp + kb1 + roff[it]);
                cp16(nb + XL_O + ssw[it], xlp + kb1 + roff[it]);
                cp16(nb + CH_O + ssw[it], chp + cb1 + roff[it]);
                cp16(nb + CL_O + ssw[it], clp + cb1 + roff[it]);
            }
            CP_COMMIT();
        }
        uint32_t bufb = sb + (uint32_t)((gg & 1) * BUFSZ);
        #pragma unroll
        for (int ks = 0; ks < 4; ks++) {
            uint32_t ah[2][4], al[2][4];
            #pragma unroll
            for (int mf = 0; mf < 2; mf++) {
                uint32_t off = (uint32_t)(a_r + mf * 16) * 128u + (uint32_t)(ks * 32 + a_c);
                uint32_t sw = SWZ(off);
                ldm_x4(ah[mf], bufb + XH_O + sw);
                ldm_x4(al[mf], bufb + XL_O + sw);
            }
            uint32_t bh[16], bl[16];
            #pragma unroll
            for (int nf2 = 0; nf2 < 4; nf2++) {
                uint32_t off = (uint32_t)(b_r + nf2 * 16) * 128u + (uint32_t)(ks * 32 + b_c);
                uint32_t sw = SWZ(off);
                ldm_x4(&bh[nf2 * 4], bufb + CH_O + sw);
                ldm_x4(&bl[nf2 * 4], bufb + CL_O + sw);
            }
            #pragma unroll
            for (int mf = 0; mf < 2; mf++)
                #pragma unroll
                for (int nf = 0; nf < 8; nf++) {
                    mma_bf16(acc[mf][nf], ah[mf], &bh[nf * 2]);
                    mma_bf16(acc[mf][nf], ah[mf], &bl[nf * 2]);
                    mma_bf16(acc[mf][nf], al[mf], &bh[nf * 2]);
                }
        }
        if ((gg & 7) == 7) {
            int nt = gg >> 3;
            int cb0 = eb + nt * 128 + wn * 64 + (lane & 3) * 2;
            #pragma unroll
            for (int mf = 0; mf < 2; mf++)
                #pragma unroll
                for (int nf = 0; nf < 8; nf++) {
                    int c = cb0 + nf * 8;
                    float v0 = acc[mf][nf][0], v1 = acc[mf][nf][1];
                    float v2 = acc[mf][nf][2], v3 = acc[mf][nf][3];
                    int s0 = mf * 2, s1 = mf * 2 + 1;
                    if (v0 > best[s0]) { best[s0] = v0; bidx[s0] = c; }
                    if (v1 > best[s0]) { best[s0] = v1; bidx[s0] = c + 1; }
                    if (v2 > best[s1]) { best[s1] = v2; bidx[s1] = c; }
                    if (v3 > best[s1]) { best[s1] = v3; bidx[s1] = c + 1; }
                    acc[mf][nf][0] = 0.f; acc[mf][nf][1] = 0.f;
                    acc[mf][nf][2] = 0.f; acc[mf][nf][3] = 0.f;
                }
        }
        if (gg + 1 < GTOT) CP_WAIT0();
        __syncthreads();
    }

    // reduce across the 4 lanes sharing each row (tie -> smaller idx),
    // then one packed atomicMax per (row, wn) into g_best.
    #pragma unroll
    for (int s = 0; s < 4; s++) {
        #pragma unroll
        for (int off = 1; off <= 2; off <<= 1) {
            float ov = __shfl_xor_sync(0xffffffffu, best[s], off);
            int   oi = __shfl_xor_sync(0xffffffffu, bidx[s], off);
            if (ov > best[s] || (ov == best[s] && oi < bidx[s])) {
                best[s] = ov; bidx[s] = oi;
            }
        }
    }
    if ((lane & 3) == 0) {
        #pragma unroll
        for (int s = 0; s < 4; s++) {
            int row = wm * 32 + (s >> 1) * 16 + (lane >> 2) + (s & 1) * 8;
            atomicMax(&g_best[m0 + row], pack_key(best[s], bidx[s]));
        }
    }
}

// ---------------- rotation-trick update per token ------------------------------
// x_n recomputed as res * stored inv-norm (bit-identical to prior g_xn path).
__global__ void rotate_update_kernel(int stage, float* __restrict__ out, int write_aux) {
    int warp = threadIdx.x >> 5;
    int lane = threadIdx.x & 31;
    int token = blockIdx.x * 8 + warp;

    float4* rr = (float4*)(g_res + (size_t)token * DIM);
    float invx = g_innorm[token];
    unsigned long long bkey = g_best[token];
    int code = (int)(0xFFFFFFFFu - (unsigned)(bkey & 0xFFFFFFFFull));
    const float4* qr = (const float4*)(g_cbn + (size_t)stage * CBSZ + (size_t)code * DIM);

    float4 xv[4], qv[4], rv[4];
    float see = 0.f, stt = 0.f, set = 0.f;
    #pragma unroll
    for (int j = 0; j < 4; j++) {
        rv[j] = rr[lane + j * 32];
        xv[j] = make_float4(rv[j].x * invx, rv[j].y * invx,
                            rv[j].z * invx, rv[j].w * invx);
        qv[j] = qr[lane + j * 32];
        see += xv[j].x * xv[j].x + xv[j].y * xv[j].y + xv[j].z * xv[j].z + xv[j].w * xv[j].w;
        stt += qv[j].x * qv[j].x + qv[j].y * qv[j].y + qv[j].z * qv[j].z + qv[j].w * qv[j].w;
        set += xv[j].x * qv[j].x + xv[j].y * qv[j].y + xv[j].z * qv[j].z + xv[j].w * qv[j].w;
    }
    see = warp_sum(see); stt = warp_sum(stt); set = warp_sum(set);

    float ns = sqrtf(see), nt = sqrtf(stt);
    float eu = see / ns;
    float eq = set / nt;
    float nw2 = 2.f + 2.f * set / (ns * nt);
    float nw = fmaxf(sqrtf(nw2), 1e-12f);
    float cw = 2.f * (eu + eq) / (nw * nw);
    float ax = (nt / ns) * (1.f - cw / ns);
    float aq = (2.f * eu - cw) / ns;
    float scc = see - 2.f * set + stt;

    float4* qo = (float4*)(out + (size_t)token * DIM);
    float rn2 = 0.f;
    float4 rnv[4];
    #pragma unroll
    for (int j = 0; j < 4; j++) {
        float4 o;
        o.x = ax * xv[j].x + aq * qv[j].x;
        o.y = ax * xv[j].y + aq * qv[j].y;
        o.z = ax * xv[j].z + aq * qv[j].z;
        o.w = ax * xv[j].w + aq * qv[j].w;
        if (stage == 0) {
            qo[lane + j * 32] = o;
        } else {
            float4 prev = qo[lane + j * 32];
            prev.x += o.x; prev.y += o.y; prev.z += o.z; prev.w += o.w;
            qo[lane + j * 32] = prev;
        }
        float4 rn;
        rn.x = rv[j].x - o.x; rn.y = rv[j].y - o.y;
        rn.z = rv[j].z - o.z; rn.w = rv[j].w - o.w;
        rr[lane + j * 32] = rn;
        rnv[j] = rn;
        rn2 += rn.x * rn.x + rn.y * rn.y + rn.z * rn.z + rn.w * rn.w;
    }
    if (stage < NQ - 1) {
        rn2 = warp_sum(rn2);
        float inv = 1.f / fmaxf(sqrtf(rn2), 1e-12f);
        if (lane == 0) g_innorm[token] = inv;
        uint2* xhw = (uint2*)(g_xh + (size_t)token * DIM);
        uint2* xlw = (uint2*)(g_xl + (size_t)token * DIM);
        #pragma unroll
        for (int j = 0; j < 4; j++) {
            float4 n = make_float4(rnv[j].x * inv, rnv[j].y * inv,
                                   rnv[j].z * inv, rnv[j].w * inv);
            uint2 h, l; split4(n, h, l);
            xhw[lane + j * 32] = h;
            xlw[lane + j * 32] = l;
        }
    }
    if (lane == 0 && write_aux)
        out[IDX_OFF + (size_t)token * NQ + stage] = (float)code;

    __shared__ float wscc[8];
    if (lane == 0) wscc[warp] = scc;
    __syncthreads();
    if (threadIdx.x == 0) {
        float s = 0.f;
        #pragma unroll
        for (int w = 0; w < 8; w++) s += wscc[w];
        atomicAdd(&g_loss[stage], (double)s);
    }
}

// ---------------- launch ------------------------------------------------------
extern "C" void kernel_launch(void* const* d_in, const int* in_sizes, int n_in,
                              void* d_out, int out_size) {
    const float* x         = (const float*)d_in[0];
    const float* codebooks = (const float*)d_in[1];
    const float* weights   = (const float*)d_in[2];
    float* out = (float*)d_out;
    int write_aux = (out_size >= OUT_FULL) ? 1 : 0;

    cudaFuncSetAttribute(sim_mma_kernel,
                         cudaFuncAttributeMaxDynamicSharedMemorySize, SMEM_MMA);
    cudaFuncSetAttribute(cb_gemm_mma_kernel,
                         cudaFuncAttributeMaxDynamicSharedMemorySize, SMEM_MMA);

    zero_loss_kernel<<<1, 32>>>();
    cb_gemm_mma_kernel<<<dim3(NC / 128, DIM / 128, NQ), 256, SMEM_MMA>>>(codebooks, weights);
    cb_norm_kernel<<<NQ * NC, 128>>>();
    init_xr_kernel<<<BN, 128>>>(x);
    for (int s = 0; s < NQ; s++) {
        clear_best_kernel<<<BN / 1024, 1024>>>();
        sim_mma_kernel<<<(BN / 128) * 8, 256, SMEM_MMA>>>(s);
        rotate_update_kernel<<<BN / 8, 256>>>(s, out, write_aux);
    }
    if (write_aux) finalize_loss_kernel<<<1, 32>>>(out);
}